// round 5
// baseline (speedup 1.0000x reference)
#include <cuda_runtime.h>
#include <math.h>

#define BS 4096
#define NV 778
#define KP 148                       // 135 pose_feat + 10 shape + 3 zero pad
#define VOUT_ELEMS (BS * NV * 3)
#define VPW 6                        // vertices per warp
#define VPB 48                       // vertices per block (8 warps)
#define BPB 64                       // batches per block (32 lanes * 2)
#define RS3 196                      // smem row stride: 64*3=192 + pad

// ---------------- scratch (device globals; no allocation) ----------------
__device__ __align__(16) float g_dirs[NV * 3 * KP];   // [v][d][k] combined posedirs|shapedirs|0
__device__ __align__(16) float g_featT[KP * BS];      // [k][b] transposed features
__device__ __align__(16) float g_se3T[192 * BS];      // [e][b] transposed SE3 (e=j*12+r*4+c)
__device__ __align__(16) float g_off[3 * BS];         // [d][b] = trans - center
__device__ float g_JS[16 * 3 * 10];                   // J_regressor @ shapedirs
__device__ float g_JT[16 * 3];                        // J_regressor @ v_template

__constant__ int c_parent[16]   = {-1,0,1,2,0,4,5,0,7,8,0,10,11,0,13,14};
__constant__ int c_neworder[21] = {0,13,14,15,16,1,2,3,17,4,5,6,18,10,11,12,19,7,8,9,20};

// ---------------- kernel 0a: build combined dirs with zero pad ----------------
__global__ void k_build_dirs(const float* __restrict__ posedirs,
                             const float* __restrict__ shapedirs) {
    int idx = blockIdx.x * blockDim.x + threadIdx.x;
    const int total = NV * 3 * KP;
    if (idx >= total) return;
    int k  = idx % KP;
    int vd = idx / KP;  // v*3+d
    float val = 0.0f;
    if (k < 135)       val = posedirs[vd * 135 + k];
    else if (k < 145)  val = shapedirs[vd * 10 + (k - 135)];
    g_dirs[idx] = val;
}

// ---------------- kernel 0b: JS / JT ----------------
__global__ void k_jreg(const float* __restrict__ Jreg,
                       const float* __restrict__ shapedirs,
                       const float* __restrict__ v_template) {
    int jd = blockIdx.x;               // 0..47 = j*3+d
    int j = jd / 3, d = jd % 3;
    int tid = threadIdx.x;             // 128 threads
    float acc[11];
#pragma unroll
    for (int i = 0; i < 11; i++) acc[i] = 0.0f;
    for (int v = tid; v < NV; v += 128) {
        float r = Jreg[j * NV + v];
        const float* sd = shapedirs + (v * 3 + d) * 10;
#pragma unroll
        for (int s = 0; s < 10; s++) acc[s] = fmaf(r, sd[s], acc[s]);
        acc[10] = fmaf(r, v_template[v * 3 + d], acc[10]);
    }
    __shared__ float red[128][11];
#pragma unroll
    for (int i = 0; i < 11; i++) red[tid][i] = acc[i];
    __syncthreads();
    for (int off = 64; off > 0; off >>= 1) {
        if (tid < off) {
#pragma unroll
            for (int i = 0; i < 11; i++) red[tid][i] += red[tid + off][i];
        }
        __syncthreads();
    }
    if (tid == 0) {
#pragma unroll
        for (int s = 0; s < 10; s++) g_JS[jd * 10 + s] = red[0][s];
        g_JT[jd] = red[0][10];
    }
}

// ---------------- kernel 1: per-batch pose/rot/SE3 chain ----------------
__global__ void k_batch(const float* __restrict__ root_rotation,
                        const float* __restrict__ pose,
                        const float* __restrict__ shape,
                        const float* __restrict__ trans,
                        const float* __restrict__ hc,
                        const float* __restrict__ hm,
                        float* __restrict__ jout) {  // points at d_out + VOUT_ELEMS
    int b = blockIdx.x * blockDim.x + threadIdx.x;
    if (b >= BS) return;

    float pz[45];
#pragma unroll
    for (int c = 0; c < 45; c++) pz[c] = pose[b * 45 + c];

    float rot[15][9];
    for (int jj = 0; jj < 15; jj++) {
        float ax = hm[3 * jj], ay = hm[3 * jj + 1], az = hm[3 * jj + 2];
        for (int c = 0; c < 45; c++) {
            float p = pz[c];
            const float* h = hc + c * 45 + 3 * jj;
            ax = fmaf(p, h[0], ax);
            ay = fmaf(p, h[1], ay);
            az = fmaf(p, h[2], az);
        }
        float a2  = ax * ax + ay * ay + az * az + 1e-12f;
        float ang = sqrtf(a2);
        float inv = 1.0f / ang;
        float ux = ax * inv, uy = ay * inv, uz = az * inv;
        float cc = cosf(ang), ss = sinf(ang), oc = 1.0f - cc;
        float R00 = cc + oc * ux * ux;
        float R01 = -ss * uz + oc * ux * uy;
        float R02 =  ss * uy + oc * ux * uz;
        float R10 =  ss * uz + oc * ux * uy;
        float R11 = cc + oc * uy * uy;
        float R12 = -ss * ux + oc * uy * uz;
        float R20 = -ss * uy + oc * ux * uz;
        float R21 =  ss * ux + oc * uy * uz;
        float R22 = cc + oc * uz * uz;
        rot[jj][0]=R00; rot[jj][1]=R01; rot[jj][2]=R02;
        rot[jj][3]=R10; rot[jj][4]=R11; rot[jj][5]=R12;
        rot[jj][6]=R20; rot[jj][7]=R21; rot[jj][8]=R22;
        // pose_feat = (R - I), stored transposed [k][b]
        g_featT[(9*jj+0)*BS + b] = R00 - 1.0f;
        g_featT[(9*jj+1)*BS + b] = R01;
        g_featT[(9*jj+2)*BS + b] = R02;
        g_featT[(9*jj+3)*BS + b] = R10;
        g_featT[(9*jj+4)*BS + b] = R11 - 1.0f;
        g_featT[(9*jj+5)*BS + b] = R12;
        g_featT[(9*jj+6)*BS + b] = R20;
        g_featT[(9*jj+7)*BS + b] = R21;
        g_featT[(9*jj+8)*BS + b] = R22 - 1.0f;
    }

    float sh[10];
#pragma unroll
    for (int s = 0; s < 10; s++) {
        sh[s] = shape[b * 10 + s];
        g_featT[(135 + s) * BS + b] = sh[s];
    }
#pragma unroll
    for (int z = 0; z < 3; z++) g_featT[(145 + z) * BS + b] = 0.0f;

    // j_tpose
    float jt[16][3];
    for (int j = 0; j < 16; j++) {
#pragma unroll
        for (int d = 0; d < 3; d++) {
            float a = g_JT[j * 3 + d];
            const float* js = g_JS + (j * 3 + d) * 10;
#pragma unroll
            for (int s = 0; s < 10; s++) a = fmaf(js[s], sh[s], a);
            jt[j][d] = a;
        }
    }

    // SE3 chain (rows 3x4)
    float A[16][12];
    {
        float Rr[9];
#pragma unroll
        for (int i = 0; i < 9; i++) Rr[i] = root_rotation[b * 9 + i];
        float jx = jt[0][0], jy = jt[0][1], jz = jt[0][2];
#pragma unroll
        for (int r = 0; r < 3; r++) {
            A[0][r*4+0] = Rr[r*3+0];
            A[0][r*4+1] = Rr[r*3+1];
            A[0][r*4+2] = Rr[r*3+2];
        }
        A[0][3]  = jx - (Rr[0]*jx + Rr[1]*jy + Rr[2]*jz);
        A[0][7]  = jy - (Rr[3]*jx + Rr[4]*jy + Rr[5]*jz);
        A[0][11] = jz - (Rr[6]*jx + Rr[7]*jy + Rr[8]*jz);
    }
    for (int i = 1; i < 16; i++) {
        int p = c_parent[i];
        const float* Ri = rot[i - 1];
        float jx = jt[i][0], jy = jt[i][1], jz = jt[i][2];
        float t0 = jx - (Ri[0]*jx + Ri[1]*jy + Ri[2]*jz);
        float t1 = jy - (Ri[3]*jx + Ri[4]*jy + Ri[5]*jz);
        float t2 = jz - (Ri[6]*jx + Ri[7]*jy + Ri[8]*jz);
        const float* P = A[p];
        float* O = A[i];
#pragma unroll
        for (int r = 0; r < 3; r++) {
            float p0 = P[r*4+0], p1 = P[r*4+1], p2 = P[r*4+2];
            O[r*4+0] = p0*Ri[0] + p1*Ri[3] + p2*Ri[6];
            O[r*4+1] = p0*Ri[1] + p1*Ri[4] + p2*Ri[7];
            O[r*4+2] = p0*Ri[2] + p1*Ri[5] + p2*Ri[8];
            O[r*4+3] = p0*t0 + p1*t1 + p2*t2 + P[r*4+3];
        }
    }
    // store SE3 TRANSPOSED: [e][b] so k_main reads are coalesced
    for (int j = 0; j < 16; j++)
#pragma unroll
        for (int e = 0; e < 12; e++) g_se3T[(j * 12 + e) * BS + b] = A[j][e];

    // center / offset
    float cx = jt[0][0], cy = jt[0][1], cz = jt[0][2];
    float ox = trans[b*3+0] - cx, oy = trans[b*3+1] - cy, oz = trans[b*3+2] - cz;
    g_off[0*BS + b] = ox;
    g_off[1*BS + b] = oy;
    g_off[2*BS + b] = oz;

    // joint outputs (non-tip entries of j_out)
    float jl[16][3];
    jl[0][0] = cx; jl[0][1] = cy; jl[0][2] = cz;
    for (int i = 1; i < 16; i++) {
        int p = c_parent[i];
        const float* P = A[p];
        float jx = jt[i][0], jy = jt[i][1], jz = jt[i][2];
        jl[i][0] = P[0]*jx + P[1]*jy + P[2]*jz  + P[3];
        jl[i][1] = P[4]*jx + P[5]*jy + P[6]*jz  + P[7];
        jl[i][2] = P[8]*jx + P[9]*jy + P[10]*jz + P[11];
    }
    for (int pos = 0; pos < 21; pos++) {
        int src = c_neworder[pos];
        if (src < 16) {
            float* jo = jout + ((size_t)b * 21 + pos) * 3;
            jo[0] = jl[src][0] + ox;
            jo[1] = jl[src][1] + oy;
            jo[2] = jl[src][2] + oz;
        }
    }
}

// ---------------- kernel 2: main fused GEMM + LBS, 6 vertices/warp, 2 batches/lane ----------------
union F4 { float4 v; float a[4]; };
union F2 { float2 v; float a[2]; };

__global__ void __launch_bounds__(256, 2) k_main(const float* __restrict__ v_template,
                                                 const float* __restrict__ weights,
                                                 float* __restrict__ out) {
    __shared__ float s_out[VPB * RS3];   // [v_local][b_local*3+d]

    int warp = threadIdx.x >> 5;
    int lane = threadIdx.x & 31;
    int vbase = blockIdx.x * VPB + warp * VPW;
    int b0 = blockIdx.y * BPB + lane * 2;

    int  vc[VPW];
    bool valid[VPW];
#pragma unroll
    for (int u = 0; u < VPW; u++) {
        int v = vbase + u;
        valid[u] = (v < NV);
        vc[u] = valid[u] ? v : (NV - 1);
    }

    const float* dbase[VPW];
#pragma unroll
    for (int u = 0; u < VPW; u++) dbase[u] = g_dirs + vc[u] * 3 * KP;

    float hx[VPW][2], hy[VPW][2], hz[VPW][2];
#pragma unroll
    for (int u = 0; u < VPW; u++)
#pragma unroll
        for (int i = 0; i < 2; i++) { hx[u][i] = 0.f; hy[u][i] = 0.f; hz[u][i] = 0.f; }

    // -------- phase 1: v_tpose GEMM over K=148 --------
    for (int k0 = 0; k0 < KP; k0 += 4) {
        F2 f[4];
#pragma unroll
        for (int kk = 0; kk < 4; kk++)
            f[kk].v = *reinterpret_cast<const float2*>(g_featT + (k0 + kk) * BS + b0);
#pragma unroll
        for (int u = 0; u < VPW; u++) {
            F4 d0, d1, d2;
            d0.v = *reinterpret_cast<const float4*>(dbase[u] + 0 * KP + k0);
            d1.v = *reinterpret_cast<const float4*>(dbase[u] + 1 * KP + k0);
            d2.v = *reinterpret_cast<const float4*>(dbase[u] + 2 * KP + k0);
#pragma unroll
            for (int kk = 0; kk < 4; kk++) {
#pragma unroll
                for (int i = 0; i < 2; i++) {
                    hx[u][i] = fmaf(d0.a[kk], f[kk].a[i], hx[u][i]);
                    hy[u][i] = fmaf(d1.a[kk], f[kk].a[i], hy[u][i]);
                    hz[u][i] = fmaf(d2.a[kk], f[kk].a[i], hz[u][i]);
                }
            }
        }
    }

    // add v_template
#pragma unroll
    for (int u = 0; u < VPW; u++) {
        float t0 = v_template[vc[u] * 3 + 0];
        float t1 = v_template[vc[u] * 3 + 1];
        float t2 = v_template[vc[u] * 3 + 2];
#pragma unroll
        for (int i = 0; i < 2; i++) { hx[u][i] += t0; hy[u][i] += t1; hz[u][i] += t2; }
    }

    // -------- phase 2: LBS blend over 16 joints --------
    float rx[VPW][2], ry[VPW][2], rz[VPW][2];
#pragma unroll
    for (int u = 0; u < VPW; u++)
#pragma unroll
        for (int i = 0; i < 2; i++) { rx[u][i] = 0.f; ry[u][i] = 0.f; rz[u][i] = 0.f; }

#pragma unroll
    for (int j = 0; j < 16; j++) {
        float w[VPW];
#pragma unroll
        for (int u = 0; u < VPW; u++) w[u] = weights[vc[u] * 16 + j];
        const float* base = g_se3T + (j * 12) * BS + b0;
#pragma unroll
        for (int r = 0; r < 3; r++) {
            F2 m0, m1, m2, m3;
            m0.v = *reinterpret_cast<const float2*>(base + (r*4+0) * BS);
            m1.v = *reinterpret_cast<const float2*>(base + (r*4+1) * BS);
            m2.v = *reinterpret_cast<const float2*>(base + (r*4+2) * BS);
            m3.v = *reinterpret_cast<const float2*>(base + (r*4+3) * BS);
#pragma unroll
            for (int u = 0; u < VPW; u++) {
#pragma unroll
                for (int i = 0; i < 2; i++) {
                    float t = fmaf(m0.a[i], hx[u][i],
                              fmaf(m1.a[i], hy[u][i],
                              fmaf(m2.a[i], hz[u][i], m3.a[i])));
                    if (r == 0) rx[u][i] = fmaf(w[u], t, rx[u][i]);
                    else if (r == 1) ry[u][i] = fmaf(w[u], t, ry[u][i]);
                    else rz[u][i] = fmaf(w[u], t, rz[u][i]);
                }
            }
        }
    }

    F2 off0, off1, off2;
    off0.v = *reinterpret_cast<const float2*>(g_off + 0 * BS + b0);
    off1.v = *reinterpret_cast<const float2*>(g_off + 1 * BS + b0);
    off2.v = *reinterpret_cast<const float2*>(g_off + 2 * BS + b0);

#pragma unroll
    for (int u = 0; u < VPW; u++) {
        int vl = warp * VPW + u;
        int v  = vbase + u;
        int pos = -1;
        if      (v == 745) pos = 4;
        else if (v == 333) pos = 8;
        else if (v == 444) pos = 12;
        else if (v == 555) pos = 16;
        else if (v == 672) pos = 20;
#pragma unroll
        for (int i = 0; i < 2; i++) {
            int bl = lane * 2 + i;
            float o0 = rx[u][i] + off0.a[i];
            float o1 = ry[u][i] + off1.a[i];
            float o2 = rz[u][i] + off2.a[i];
            if (valid[u]) {
                s_out[vl * RS3 + bl * 3 + 0] = o0;
                s_out[vl * RS3 + bl * 3 + 1] = o1;
                s_out[vl * RS3 + bl * 3 + 2] = o2;
            }
            if (pos >= 0) {
                int b = b0 + i;
                float* jo = out + (size_t)VOUT_ELEMS + ((size_t)b * 21 + pos) * 3;
                jo[0] = o0; jo[1] = o1; jo[2] = o2;
            }
        }
    }

    __syncthreads();

    // cooperative coalesced readout: per batch, the block's 48 vertices are
    // 144 contiguous floats in out[(b*NV + v_base)*3 ...]
    int v_base = blockIdx.x * VPB;
    int b_base = blockIdx.y * BPB;
    int nv_here = NV - v_base;
    if (nv_here > VPB) nv_here = VPB;
    int row_floats = nv_here * 3;
#pragma unroll 4
    for (int t = threadIdx.x; t < BPB * (VPB * 3); t += 256) {
        int b_local = t / (VPB * 3);
        int e = t % (VPB * 3);
        if (e < row_floats) {
            int v_local = e / 3;
            int d = e - v_local * 3;
            out[((size_t)(b_base + b_local) * NV + v_base) * 3 + e] =
                s_out[v_local * RS3 + b_local * 3 + d];
        }
    }
}

// ---------------- launch ----------------
extern "C" void kernel_launch(void* const* d_in, const int* in_sizes, int n_in,
                              void* d_out, int out_size) {
    const float* root_rotation = (const float*)d_in[0];
    const float* pose          = (const float*)d_in[1];
    const float* shape         = (const float*)d_in[2];
    const float* trans         = (const float*)d_in[3];
    const float* hc            = (const float*)d_in[4];
    const float* hm            = (const float*)d_in[5];
    const float* shapedirs     = (const float*)d_in[6];
    const float* posedirs      = (const float*)d_in[7];
    const float* v_template    = (const float*)d_in[8];
    const float* Jreg          = (const float*)d_in[9];
    const float* weights       = (const float*)d_in[10];
    float* out = (float*)d_out;

    int dirs_total = NV * 3 * KP;
    k_build_dirs<<<(dirs_total + 255) / 256, 256>>>(posedirs, shapedirs);
    k_jreg<<<48, 128>>>(Jreg, shapedirs, v_template);
    k_batch<<<BS / 128, 128>>>(root_rotation, pose, shape, trans, hc, hm,
                               out + VOUT_ELEMS);
    dim3 grid((NV + VPB - 1) / VPB, BS / BPB);
    k_main<<<grid, 256>>>(v_template, weights, out);
}

// round 6
// speedup vs baseline: 1.0197x; 1.0197x over previous
#include <cuda_runtime.h>
#include <math.h>

#define BS 4096
#define NV 778
#define KP 148                       // 135 pose_feat + 10 shape + 3 zero pad
#define VOUT_ELEMS (BS * NV * 3)
#define RS 388                       // smem out row stride (floats), 384 data + pad

// ---------------- scratch (device globals; no allocation) ----------------
__device__ __align__(16) float g_dirs2[NV * 3 * KP * 2]; // [v][d][k][2] duplicated pairs
__device__ __align__(16) float g_featT[KP * BS];      // [k][b] transposed features
__device__ __align__(16) float g_se3T[192 * BS];      // [e][b] transposed SE3 (e=j*12+r*4+c)
__device__ __align__(16) float g_off[3 * BS];         // [d][b] = trans - center
__device__ float g_JS[16 * 3 * 10];                   // J_regressor @ shapedirs
__device__ float g_JT[16 * 3];                        // J_regressor @ v_template

__constant__ int c_parent[16]   = {-1,0,1,2,0,4,5,0,7,8,0,10,11,0,13,14};
__constant__ int c_neworder[21] = {0,13,14,15,16,1,2,3,17,4,5,6,18,10,11,12,19,7,8,9,20};

// ---------------- f32x2 packed helpers ----------------
typedef unsigned long long ull;
union U2 { ulonglong2 v; ull p[2]; };

__device__ __forceinline__ ull fma2(ull a, ull b, ull c) {
    ull d;
    asm("fma.rn.f32x2 %0, %1, %2, %3;" : "=l"(d) : "l"(a), "l"(b), "l"(c));
    return d;
}
__device__ __forceinline__ ull add2(ull a, ull b) {
    ull d;
    asm("add.rn.f32x2 %0, %1, %2;" : "=l"(d) : "l"(a), "l"(b));
    return d;
}
__device__ __forceinline__ ull pack2(float x, float y) {
    ull d;
    asm("mov.b64 %0, {%1, %2};" : "=l"(d) : "f"(x), "f"(y));
    return d;
}
__device__ __forceinline__ void unpack2(ull p, float& x, float& y) {
    asm("mov.b64 {%0, %1}, %2;" : "=f"(x), "=f"(y) : "l"(p));
}

// ---------------- kernel 0a: build duplicated dirs with zero pad ----------------
__global__ void k_build_dirs(const float* __restrict__ posedirs,
                             const float* __restrict__ shapedirs) {
    int idx = blockIdx.x * blockDim.x + threadIdx.x;
    const int total = NV * 3 * KP;
    if (idx >= total) return;
    int k  = idx % KP;
    int vd = idx / KP;  // v*3+d
    float val = 0.0f;
    if (k < 135)       val = posedirs[vd * 135 + k];
    else if (k < 145)  val = shapedirs[vd * 10 + (k - 135)];
    g_dirs2[idx * 2 + 0] = val;
    g_dirs2[idx * 2 + 1] = val;
}

// ---------------- kernel 0b: JS / JT ----------------
__global__ void k_jreg(const float* __restrict__ Jreg,
                       const float* __restrict__ shapedirs,
                       const float* __restrict__ v_template) {
    int jd = blockIdx.x;               // 0..47 = j*3+d
    int j = jd / 3, d = jd % 3;
    int tid = threadIdx.x;             // 128 threads
    float acc[11];
#pragma unroll
    for (int i = 0; i < 11; i++) acc[i] = 0.0f;
    for (int v = tid; v < NV; v += 128) {
        float r = Jreg[j * NV + v];
        const float* sd = shapedirs + (v * 3 + d) * 10;
#pragma unroll
        for (int s = 0; s < 10; s++) acc[s] = fmaf(r, sd[s], acc[s]);
        acc[10] = fmaf(r, v_template[v * 3 + d], acc[10]);
    }
    __shared__ float red[128][11];
#pragma unroll
    for (int i = 0; i < 11; i++) red[tid][i] = acc[i];
    __syncthreads();
    for (int off = 64; off > 0; off >>= 1) {
        if (tid < off) {
#pragma unroll
            for (int i = 0; i < 11; i++) red[tid][i] += red[tid + off][i];
        }
        __syncthreads();
    }
    if (tid == 0) {
#pragma unroll
        for (int s = 0; s < 10; s++) g_JS[jd * 10 + s] = red[0][s];
        g_JT[jd] = red[0][10];
    }
}

// ---------------- kernel 1: per-batch pose/rot/SE3 chain ----------------
__global__ void k_batch(const float* __restrict__ root_rotation,
                        const float* __restrict__ pose,
                        const float* __restrict__ shape,
                        const float* __restrict__ trans,
                        const float* __restrict__ hc,
                        const float* __restrict__ hm,
                        float* __restrict__ jout) {  // points at d_out + VOUT_ELEMS
    int b = blockIdx.x * blockDim.x + threadIdx.x;
    if (b >= BS) return;

    float pz[45];
#pragma unroll
    for (int c = 0; c < 45; c++) pz[c] = pose[b * 45 + c];

    float rot[15][9];
    for (int jj = 0; jj < 15; jj++) {
        float ax = hm[3 * jj], ay = hm[3 * jj + 1], az = hm[3 * jj + 2];
        for (int c = 0; c < 45; c++) {
            float p = pz[c];
            const float* h = hc + c * 45 + 3 * jj;
            ax = fmaf(p, h[0], ax);
            ay = fmaf(p, h[1], ay);
            az = fmaf(p, h[2], az);
        }
        float a2  = ax * ax + ay * ay + az * az + 1e-12f;
        float ang = sqrtf(a2);
        float inv = 1.0f / ang;
        float ux = ax * inv, uy = ay * inv, uz = az * inv;
        float cc = cosf(ang), ss = sinf(ang), oc = 1.0f - cc;
        float R00 = cc + oc * ux * ux;
        float R01 = -ss * uz + oc * ux * uy;
        float R02 =  ss * uy + oc * ux * uz;
        float R10 =  ss * uz + oc * ux * uy;
        float R11 = cc + oc * uy * uy;
        float R12 = -ss * ux + oc * uy * uz;
        float R20 = -ss * uy + oc * ux * uz;
        float R21 =  ss * ux + oc * uy * uz;
        float R22 = cc + oc * uz * uz;
        rot[jj][0]=R00; rot[jj][1]=R01; rot[jj][2]=R02;
        rot[jj][3]=R10; rot[jj][4]=R11; rot[jj][5]=R12;
        rot[jj][6]=R20; rot[jj][7]=R21; rot[jj][8]=R22;
        // pose_feat = (R - I), stored transposed [k][b]
        g_featT[(9*jj+0)*BS + b] = R00 - 1.0f;
        g_featT[(9*jj+1)*BS + b] = R01;
        g_featT[(9*jj+2)*BS + b] = R02;
        g_featT[(9*jj+3)*BS + b] = R10;
        g_featT[(9*jj+4)*BS + b] = R11 - 1.0f;
        g_featT[(9*jj+5)*BS + b] = R12;
        g_featT[(9*jj+6)*BS + b] = R20;
        g_featT[(9*jj+7)*BS + b] = R21;
        g_featT[(9*jj+8)*BS + b] = R22 - 1.0f;
    }

    float sh[10];
#pragma unroll
    for (int s = 0; s < 10; s++) {
        sh[s] = shape[b * 10 + s];
        g_featT[(135 + s) * BS + b] = sh[s];
    }
#pragma unroll
    for (int z = 0; z < 3; z++) g_featT[(145 + z) * BS + b] = 0.0f;

    // j_tpose
    float jt[16][3];
    for (int j = 0; j < 16; j++) {
#pragma unroll
        for (int d = 0; d < 3; d++) {
            float a = g_JT[j * 3 + d];
            const float* js = g_JS + (j * 3 + d) * 10;
#pragma unroll
            for (int s = 0; s < 10; s++) a = fmaf(js[s], sh[s], a);
            jt[j][d] = a;
        }
    }

    // SE3 chain (rows 3x4)
    float A[16][12];
    {
        float Rr[9];
#pragma unroll
        for (int i = 0; i < 9; i++) Rr[i] = root_rotation[b * 9 + i];
        float jx = jt[0][0], jy = jt[0][1], jz = jt[0][2];
#pragma unroll
        for (int r = 0; r < 3; r++) {
            A[0][r*4+0] = Rr[r*3+0];
            A[0][r*4+1] = Rr[r*3+1];
            A[0][r*4+2] = Rr[r*3+2];
        }
        A[0][3]  = jx - (Rr[0]*jx + Rr[1]*jy + Rr[2]*jz);
        A[0][7]  = jy - (Rr[3]*jx + Rr[4]*jy + Rr[5]*jz);
        A[0][11] = jz - (Rr[6]*jx + Rr[7]*jy + Rr[8]*jz);
    }
    for (int i = 1; i < 16; i++) {
        int p = c_parent[i];
        const float* Ri = rot[i - 1];
        float jx = jt[i][0], jy = jt[i][1], jz = jt[i][2];
        float t0 = jx - (Ri[0]*jx + Ri[1]*jy + Ri[2]*jz);
        float t1 = jy - (Ri[3]*jx + Ri[4]*jy + Ri[5]*jz);
        float t2 = jz - (Ri[6]*jx + Ri[7]*jy + Ri[8]*jz);
        const float* P = A[p];
        float* O = A[i];
#pragma unroll
        for (int r = 0; r < 3; r++) {
            float p0 = P[r*4+0], p1 = P[r*4+1], p2 = P[r*4+2];
            O[r*4+0] = p0*Ri[0] + p1*Ri[3] + p2*Ri[6];
            O[r*4+1] = p0*Ri[1] + p1*Ri[4] + p2*Ri[7];
            O[r*4+2] = p0*Ri[2] + p1*Ri[5] + p2*Ri[8];
            O[r*4+3] = p0*t0 + p1*t1 + p2*t2 + P[r*4+3];
        }
    }
    // store SE3 TRANSPOSED: [e][b] so k_main reads are coalesced
    for (int j = 0; j < 16; j++)
#pragma unroll
        for (int e = 0; e < 12; e++) g_se3T[(j * 12 + e) * BS + b] = A[j][e];

    // center / offset
    float cx = jt[0][0], cy = jt[0][1], cz = jt[0][2];
    float ox = trans[b*3+0] - cx, oy = trans[b*3+1] - cy, oz = trans[b*3+2] - cz;
    g_off[0*BS + b] = ox;
    g_off[1*BS + b] = oy;
    g_off[2*BS + b] = oz;

    // joint outputs (non-tip entries of j_out)
    float jl[16][3];
    jl[0][0] = cx; jl[0][1] = cy; jl[0][2] = cz;
    for (int i = 1; i < 16; i++) {
        int p = c_parent[i];
        const float* P = A[p];
        float jx = jt[i][0], jy = jt[i][1], jz = jt[i][2];
        jl[i][0] = P[0]*jx + P[1]*jy + P[2]*jz  + P[3];
        jl[i][1] = P[4]*jx + P[5]*jy + P[6]*jz  + P[7];
        jl[i][2] = P[8]*jx + P[9]*jy + P[10]*jz + P[11];
    }
    for (int pos = 0; pos < 21; pos++) {
        int src = c_neworder[pos];
        if (src < 16) {
            float* jo = jout + ((size_t)b * 21 + pos) * 3;
            jo[0] = jl[src][0] + ox;
            jo[1] = jl[src][1] + oy;
            jo[2] = jl[src][2] + oz;
        }
    }
}

// ---------------- kernel 2: fused GEMM + LBS, 2 v/warp, 4 b/lane, f32x2 packed ----------------
__global__ void __launch_bounds__(256, 2) k_main(const float* __restrict__ v_template,
                                                 const float* __restrict__ weights,
                                                 float* __restrict__ out) {
    __shared__ float s_out[16 * RS];   // [v_local][b_local*3+d]

    int warp = threadIdx.x >> 5;
    int lane = threadIdx.x & 31;
    int v0 = blockIdx.x * 16 + warp * 2;
    int v1 = v0 + 1;
    bool valid0 = (v0 < NV);
    bool valid1 = (v1 < NV);
    int v0c = valid0 ? v0 : (NV - 1);
    int v1c = valid1 ? v1 : (NV - 1);
    int b0 = blockIdx.y * 128 + lane * 4;

    // accumulators: [dim][pair], pairs cover batches (b0,b0+1) and (b0+2,b0+3)
    ull hA[3][2], hB[3][2];
#pragma unroll
    for (int d = 0; d < 3; d++)
#pragma unroll
        for (int p = 0; p < 2; p++) { hA[d][p] = 0ULL; hB[d][p] = 0ULL; }

    const float* baseA = g_dirs2 + v0c * 3 * KP * 2;
    const float* baseB = g_dirs2 + v1c * 3 * KP * 2;

    // -------- phase 1: v_tpose GEMM over K=148 (packed f32x2) --------
    for (int k0 = 0; k0 < KP; k0 += 4) {
        U2 f[4];
#pragma unroll
        for (int kk = 0; kk < 4; kk++)
            f[kk].v = *reinterpret_cast<const ulonglong2*>(g_featT + (k0 + kk) * BS + b0);
#pragma unroll
        for (int kk2 = 0; kk2 < 4; kk2 += 2) {
            // dup-pairs: x = [c_k,c_k], y = [c_{k+1},c_{k+1}]
            U2 a0, a1, a2, c0, c1, c2;
            a0.v = *reinterpret_cast<const ulonglong2*>(baseA + (0 * KP + k0 + kk2) * 2);
            a1.v = *reinterpret_cast<const ulonglong2*>(baseA + (1 * KP + k0 + kk2) * 2);
            a2.v = *reinterpret_cast<const ulonglong2*>(baseA + (2 * KP + k0 + kk2) * 2);
            c0.v = *reinterpret_cast<const ulonglong2*>(baseB + (0 * KP + k0 + kk2) * 2);
            c1.v = *reinterpret_cast<const ulonglong2*>(baseB + (1 * KP + k0 + kk2) * 2);
            c2.v = *reinterpret_cast<const ulonglong2*>(baseB + (2 * KP + k0 + kk2) * 2);
#pragma unroll
            for (int t = 0; t < 2; t++) {
#pragma unroll
                for (int p = 0; p < 2; p++) {
                    ull fp = f[kk2 + t].p[p];
                    hA[0][p] = fma2(a0.p[t], fp, hA[0][p]);
                    hA[1][p] = fma2(a1.p[t], fp, hA[1][p]);
                    hA[2][p] = fma2(a2.p[t], fp, hA[2][p]);
                    hB[0][p] = fma2(c0.p[t], fp, hB[0][p]);
                    hB[1][p] = fma2(c1.p[t], fp, hB[1][p]);
                    hB[2][p] = fma2(c2.p[t], fp, hB[2][p]);
                }
            }
        }
    }

    // add v_template
#pragma unroll
    for (int d = 0; d < 3; d++) {
        float tA = v_template[v0c * 3 + d];
        float tB = v_template[v1c * 3 + d];
        ull tAp = pack2(tA, tA);
        ull tBp = pack2(tB, tB);
#pragma unroll
        for (int p = 0; p < 2; p++) {
            hA[d][p] = add2(hA[d][p], tAp);
            hB[d][p] = add2(hB[d][p], tBp);
        }
    }

    // -------- phase 2: LBS blend over 16 joints (packed f32x2) --------
    ull rA[3][2], rB[3][2];
#pragma unroll
    for (int d = 0; d < 3; d++)
#pragma unroll
        for (int p = 0; p < 2; p++) { rA[d][p] = 0ULL; rB[d][p] = 0ULL; }

#pragma unroll
    for (int j = 0; j < 16; j++) {
        float wA = weights[v0c * 16 + j];
        float wB = weights[v1c * 16 + j];
        ull wAp = pack2(wA, wA);
        ull wBp = pack2(wB, wB);
        const float* base = g_se3T + (j * 12) * BS + b0;
#pragma unroll
        for (int r = 0; r < 3; r++) {
            U2 m0, m1, m2, m3;
            m0.v = *reinterpret_cast<const ulonglong2*>(base + (r*4+0) * BS);
            m1.v = *reinterpret_cast<const ulonglong2*>(base + (r*4+1) * BS);
            m2.v = *reinterpret_cast<const ulonglong2*>(base + (r*4+2) * BS);
            m3.v = *reinterpret_cast<const ulonglong2*>(base + (r*4+3) * BS);
#pragma unroll
            for (int p = 0; p < 2; p++) {
                ull tA = fma2(m0.p[p], hA[0][p],
                         fma2(m1.p[p], hA[1][p],
                         fma2(m2.p[p], hA[2][p], m3.p[p])));
                rA[r][p] = fma2(wAp, tA, rA[r][p]);
                ull tB = fma2(m0.p[p], hB[0][p],
                         fma2(m1.p[p], hB[1][p],
                         fma2(m2.p[p], hB[2][p], m3.p[p])));
                rB[r][p] = fma2(wBp, tB, rB[r][p]);
            }
        }
    }

    // add offset, unpack, store
    U2 off[3];
#pragma unroll
    for (int d = 0; d < 3; d++)
        off[d].v = *reinterpret_cast<const ulonglong2*>(g_off + d * BS + b0);

    int posA = -1, posB = -1;
    if      (v0 == 745) posA = 4;
    else if (v0 == 333) posA = 8;
    else if (v0 == 444) posA = 12;
    else if (v0 == 555) posA = 16;
    else if (v0 == 672) posA = 20;
    if      (v1 == 745) posB = 4;
    else if (v1 == 333) posB = 8;
    else if (v1 == 444) posB = 12;
    else if (v1 == 555) posB = 16;
    else if (v1 == 672) posB = 20;

    int vl0 = warp * 2;
    int vl1 = vl0 + 1;
#pragma unroll
    for (int p = 0; p < 2; p++) {
        float oA[3][2], oB[3][2];
#pragma unroll
        for (int d = 0; d < 3; d++) {
            ull sA = add2(rA[d][p], off[d].p[p]);
            ull sB = add2(rB[d][p], off[d].p[p]);
            unpack2(sA, oA[d][0], oA[d][1]);
            unpack2(sB, oB[d][0], oB[d][1]);
        }
#pragma unroll
        for (int i = 0; i < 2; i++) {
            int bl = lane * 4 + p * 2 + i;
            if (valid0) {
                s_out[vl0 * RS + bl * 3 + 0] = oA[0][i];
                s_out[vl0 * RS + bl * 3 + 1] = oA[1][i];
                s_out[vl0 * RS + bl * 3 + 2] = oA[2][i];
            }
            if (valid1) {
                s_out[vl1 * RS + bl * 3 + 0] = oB[0][i];
                s_out[vl1 * RS + bl * 3 + 1] = oB[1][i];
                s_out[vl1 * RS + bl * 3 + 2] = oB[2][i];
            }
            if (posA >= 0) {
                int b = b0 + p * 2 + i;
                float* jo = out + (size_t)VOUT_ELEMS + ((size_t)b * 21 + posA) * 3;
                jo[0] = oA[0][i]; jo[1] = oA[1][i]; jo[2] = oA[2][i];
            }
            if (posB >= 0) {
                int b = b0 + p * 2 + i;
                float* jo = out + (size_t)VOUT_ELEMS + ((size_t)b * 21 + posB) * 3;
                jo[0] = oB[0][i]; jo[1] = oB[1][i]; jo[2] = oB[2][i];
            }
        }
    }

    __syncthreads();

    // cooperative coalesced readout: per batch, the block's 16 vertices are
    // 48 contiguous floats in out[(b*NV + v_base)*3 ...]
    int v_base = blockIdx.x * 16;
    int b_base = blockIdx.y * 128;
    int nv_here = NV - v_base;
    if (nv_here > 16) nv_here = 16;
    int row_floats = nv_here * 3;
#pragma unroll 4
    for (int t = threadIdx.x; t < 128 * 48; t += 256) {
        int b_local = t / 48;
        int e = t % 48;
        if (e < row_floats) {
            int v_local = e / 3;
            int d = e - v_local * 3;
            out[((size_t)(b_base + b_local) * NV + v_base) * 3 + e] =
                s_out[v_local * RS + b_local * 3 + d];
        }
    }
}

// ---------------- launch ----------------
extern "C" void kernel_launch(void* const* d_in, const int* in_sizes, int n_in,
                              void* d_out, int out_size) {
    const float* root_rotation = (const float*)d_in[0];
    const float* pose          = (const float*)d_in[1];
    const float* shape         = (const float*)d_in[2];
    const float* trans         = (const float*)d_in[3];
    const float* hc            = (const float*)d_in[4];
    const float* hm            = (const float*)d_in[5];
    const float* shapedirs     = (const float*)d_in[6];
    const float* posedirs      = (const float*)d_in[7];
    const float* v_template    = (const float*)d_in[8];
    const float* Jreg          = (const float*)d_in[9];
    const float* weights       = (const float*)d_in[10];
    float* out = (float*)d_out;

    int dirs_total = NV * 3 * KP;
    k_build_dirs<<<(dirs_total + 255) / 256, 256>>>(posedirs, shapedirs);
    k_jreg<<<48, 128>>>(Jreg, shapedirs, v_template);
    k_batch<<<BS / 128, 128>>>(root_rotation, pose, shape, trans, hc, hm,
                               out + VOUT_ELEMS);
    dim3 grid((NV + 15) / 16, BS / 128);
    k_main<<<grid, 256>>>(v_template, weights, out);
}

// round 7
// speedup vs baseline: 1.0940x; 1.0729x over previous
#include <cuda_runtime.h>
#include <math.h>

#define BS 4096
#define NV 778
#define KP 148
#define KPAD 152                     // K padded to 19*8
#define MROWS 2334                   // NV*3
#define MP 2432                      // M padded to 19*128
#define VOUT_ELEMS (BS * NV * 3)
#define RS 388                       // smem out row stride (floats)

typedef unsigned long long ull;
union U2 { ulonglong2 v; ull p[2]; };
union F4 { float4 v; float a[4]; };

__device__ __forceinline__ ull fma2(ull a, ull b, ull c) {
    ull d;
    asm("fma.rn.f32x2 %0, %1, %2, %3;" : "=l"(d) : "l"(a), "l"(b), "l"(c));
    return d;
}
__device__ __forceinline__ void unpack2(ull p, float& x, float& y) {
    asm("mov.b64 {%0, %1}, %2;" : "=f"(x), "=f"(y) : "l"(p));
}

// ---------------- scratch ----------------
__device__ __align__(16) float g_dirsT[KPAD * MP];    // [k][m] transposed dirs, zero-padded
__device__ __align__(16) float g_featT[KPAD * BS];    // [k][b] features, zero-padded
__device__ __align__(16) float g_h[MROWS * BS];       // [vd][b] v_tpose
__device__ __align__(16) float g_se3T[192 * BS];      // [e][b]
__device__ __align__(16) float g_off[3 * BS];         // [d][b]
__device__ float g_JS[16 * 3 * 10];
__device__ float g_JT[16 * 3];

__constant__ int c_parent[16]   = {-1,0,1,2,0,4,5,0,7,8,0,10,11,0,13,14};
__constant__ int c_neworder[21] = {0,13,14,15,16,1,2,3,17,4,5,6,18,10,11,12,19,7,8,9,20};

// ---------------- kernel 0a: build transposed dirs with zero pad ----------------
__global__ void k_build_dirsT(const float* __restrict__ posedirs,
                              const float* __restrict__ shapedirs) {
    int idx = blockIdx.x * blockDim.x + threadIdx.x;
    if (idx >= KPAD * MP) return;
    int m = idx % MP;
    int k = idx / MP;
    float val = 0.0f;
    if (m < MROWS) {
        if (k < 135)      val = posedirs[m * 135 + k];
        else if (k < 145) val = shapedirs[m * 10 + (k - 135)];
    }
    g_dirsT[idx] = val;
}

// ---------------- kernel 0b: JS / JT ----------------
__global__ void k_jreg(const float* __restrict__ Jreg,
                       const float* __restrict__ shapedirs,
                       const float* __restrict__ v_template) {
    int jd = blockIdx.x;
    int j = jd / 3, d = jd % 3;
    int tid = threadIdx.x;
    float acc[11];
#pragma unroll
    for (int i = 0; i < 11; i++) acc[i] = 0.0f;
    for (int v = tid; v < NV; v += 128) {
        float r = Jreg[j * NV + v];
        const float* sd = shapedirs + (v * 3 + d) * 10;
#pragma unroll
        for (int s = 0; s < 10; s++) acc[s] = fmaf(r, sd[s], acc[s]);
        acc[10] = fmaf(r, v_template[v * 3 + d], acc[10]);
    }
    __shared__ float red[128][11];
#pragma unroll
    for (int i = 0; i < 11; i++) red[tid][i] = acc[i];
    __syncthreads();
    for (int off = 64; off > 0; off >>= 1) {
        if (tid < off) {
#pragma unroll
            for (int i = 0; i < 11; i++) red[tid][i] += red[tid + off][i];
        }
        __syncthreads();
    }
    if (tid == 0) {
#pragma unroll
        for (int s = 0; s < 10; s++) g_JS[jd * 10 + s] = red[0][s];
        g_JT[jd] = red[0][10];
    }
}

// ---------------- kernel 1: per-batch pose/rot/SE3 chain ----------------
__global__ void k_batch(const float* __restrict__ root_rotation,
                        const float* __restrict__ pose,
                        const float* __restrict__ shape,
                        const float* __restrict__ trans,
                        const float* __restrict__ hc,
                        const float* __restrict__ hm,
                        float* __restrict__ jout) {
    int b = blockIdx.x * blockDim.x + threadIdx.x;
    if (b >= BS) return;

    float pz[45];
#pragma unroll
    for (int c = 0; c < 45; c++) pz[c] = pose[b * 45 + c];

    float rot[15][9];
    for (int jj = 0; jj < 15; jj++) {
        float ax = hm[3 * jj], ay = hm[3 * jj + 1], az = hm[3 * jj + 2];
        for (int c = 0; c < 45; c++) {
            float p = pz[c];
            const float* h = hc + c * 45 + 3 * jj;
            ax = fmaf(p, h[0], ax);
            ay = fmaf(p, h[1], ay);
            az = fmaf(p, h[2], az);
        }
        float a2  = ax * ax + ay * ay + az * az + 1e-12f;
        float ang = sqrtf(a2);
        float inv = 1.0f / ang;
        float ux = ax * inv, uy = ay * inv, uz = az * inv;
        float cc = cosf(ang), ss = sinf(ang), oc = 1.0f - cc;
        float R00 = cc + oc * ux * ux;
        float R01 = -ss * uz + oc * ux * uy;
        float R02 =  ss * uy + oc * ux * uz;
        float R10 =  ss * uz + oc * ux * uy;
        float R11 = cc + oc * uy * uy;
        float R12 = -ss * ux + oc * uy * uz;
        float R20 = -ss * uy + oc * ux * uz;
        float R21 =  ss * ux + oc * uy * uz;
        float R22 = cc + oc * uz * uz;
        rot[jj][0]=R00; rot[jj][1]=R01; rot[jj][2]=R02;
        rot[jj][3]=R10; rot[jj][4]=R11; rot[jj][5]=R12;
        rot[jj][6]=R20; rot[jj][7]=R21; rot[jj][8]=R22;
        g_featT[(9*jj+0)*BS + b] = R00 - 1.0f;
        g_featT[(9*jj+1)*BS + b] = R01;
        g_featT[(9*jj+2)*BS + b] = R02;
        g_featT[(9*jj+3)*BS + b] = R10;
        g_featT[(9*jj+4)*BS + b] = R11 - 1.0f;
        g_featT[(9*jj+5)*BS + b] = R12;
        g_featT[(9*jj+6)*BS + b] = R20;
        g_featT[(9*jj+7)*BS + b] = R21;
        g_featT[(9*jj+8)*BS + b] = R22 - 1.0f;
    }

    float sh[10];
#pragma unroll
    for (int s = 0; s < 10; s++) {
        sh[s] = shape[b * 10 + s];
        g_featT[(135 + s) * BS + b] = sh[s];
    }
#pragma unroll
    for (int z = 145; z < KPAD; z++) g_featT[z * BS + b] = 0.0f;

    float jt[16][3];
    for (int j = 0; j < 16; j++) {
#pragma unroll
        for (int d = 0; d < 3; d++) {
            float a = g_JT[j * 3 + d];
            const float* js = g_JS + (j * 3 + d) * 10;
#pragma unroll
            for (int s = 0; s < 10; s++) a = fmaf(js[s], sh[s], a);
            jt[j][d] = a;
        }
    }

    float A[16][12];
    {
        float Rr[9];
#pragma unroll
        for (int i = 0; i < 9; i++) Rr[i] = root_rotation[b * 9 + i];
        float jx = jt[0][0], jy = jt[0][1], jz = jt[0][2];
#pragma unroll
        for (int r = 0; r < 3; r++) {
            A[0][r*4+0] = Rr[r*3+0];
            A[0][r*4+1] = Rr[r*3+1];
            A[0][r*4+2] = Rr[r*3+2];
        }
        A[0][3]  = jx - (Rr[0]*jx + Rr[1]*jy + Rr[2]*jz);
        A[0][7]  = jy - (Rr[3]*jx + Rr[4]*jy + Rr[5]*jz);
        A[0][11] = jz - (Rr[6]*jx + Rr[7]*jy + Rr[8]*jz);
    }
    for (int i = 1; i < 16; i++) {
        int p = c_parent[i];
        const float* Ri = rot[i - 1];
        float jx = jt[i][0], jy = jt[i][1], jz = jt[i][2];
        float t0 = jx - (Ri[0]*jx + Ri[1]*jy + Ri[2]*jz);
        float t1 = jy - (Ri[3]*jx + Ri[4]*jy + Ri[5]*jz);
        float t2 = jz - (Ri[6]*jx + Ri[7]*jy + Ri[8]*jz);
        const float* P = A[p];
        float* O = A[i];
#pragma unroll
        for (int r = 0; r < 3; r++) {
            float p0 = P[r*4+0], p1 = P[r*4+1], p2 = P[r*4+2];
            O[r*4+0] = p0*Ri[0] + p1*Ri[3] + p2*Ri[6];
            O[r*4+1] = p0*Ri[1] + p1*Ri[4] + p2*Ri[7];
            O[r*4+2] = p0*Ri[2] + p1*Ri[5] + p2*Ri[8];
            O[r*4+3] = p0*t0 + p1*t1 + p2*t2 + P[r*4+3];
        }
    }
    for (int j = 0; j < 16; j++)
#pragma unroll
        for (int e = 0; e < 12; e++) g_se3T[(j * 12 + e) * BS + b] = A[j][e];

    float cx = jt[0][0], cy = jt[0][1], cz = jt[0][2];
    float ox = trans[b*3+0] - cx, oy = trans[b*3+1] - cy, oz = trans[b*3+2] - cz;
    g_off[0*BS + b] = ox;
    g_off[1*BS + b] = oy;
    g_off[2*BS + b] = oz;

    float jl[16][3];
    jl[0][0] = cx; jl[0][1] = cy; jl[0][2] = cz;
    for (int i = 1; i < 16; i++) {
        int p = c_parent[i];
        const float* P = A[p];
        float jx = jt[i][0], jy = jt[i][1], jz = jt[i][2];
        jl[i][0] = P[0]*jx + P[1]*jy + P[2]*jz  + P[3];
        jl[i][1] = P[4]*jx + P[5]*jy + P[6]*jz  + P[7];
        jl[i][2] = P[8]*jx + P[9]*jy + P[10]*jz + P[11];
    }
    for (int pos = 0; pos < 21; pos++) {
        int src = c_neworder[pos];
        if (src < 16) {
            float* jo = jout + ((size_t)b * 21 + pos) * 3;
            jo[0] = jl[src][0] + ox;
            jo[1] = jl[src][1] + oy;
            jo[2] = jl[src][2] + oz;
        }
    }
}

// ---------------- kernel 2: tiled SGEMM (FFMA2): g_h = dirsT^T @ featT + vt ----------------
// block tile 128(M) x 128(N), 256 threads, 8x8 micro-tile, K in steps of 8, double-buffered
__global__ void __launch_bounds__(256, 2) k_gemm(const float* __restrict__ v_template) {
    __shared__ float As[2][8][256];   // m duplicated pairs
    __shared__ float Bs[2][8][128];

    int tid = threadIdx.x;
    int bblk = blockIdx.x * 128;
    int mblk = blockIdx.y * 128;
    int lk  = tid >> 5;           // 0..7
    int l4  = (tid & 31) * 4;     // 0..124

    int tx = tid & 15;            // n dimension
    int ty = tid >> 4;            // m dimension

    ull c[8][4];
#pragma unroll
    for (int m = 0; m < 8; m++)
#pragma unroll
        for (int p = 0; p < 4; p++) c[m][p] = 0ULL;

    // prologue: load step 0
    F4 a4, b4;
    a4.v = *reinterpret_cast<const float4*>(g_dirsT + lk * MP + mblk + l4);
    b4.v = *reinterpret_cast<const float4*>(g_featT + lk * BS + bblk + l4);
    {
        float4 d0 = make_float4(a4.a[0], a4.a[0], a4.a[1], a4.a[1]);
        float4 d1 = make_float4(a4.a[2], a4.a[2], a4.a[3], a4.a[3]);
        *reinterpret_cast<float4*>(&As[0][lk][2 * l4])     = d0;
        *reinterpret_cast<float4*>(&As[0][lk][2 * l4 + 4]) = d1;
        *reinterpret_cast<float4*>(&Bs[0][lk][l4]) = b4.v;
    }
    __syncthreads();

    for (int s = 0; s < 19; s++) {
        int cur = s & 1;
        bool hasNext = (s + 1 < 19);
        if (hasNext) {
            a4.v = *reinterpret_cast<const float4*>(g_dirsT + ((s+1)*8 + lk) * MP + mblk + l4);
            b4.v = *reinterpret_cast<const float4*>(g_featT + ((s+1)*8 + lk) * BS + bblk + l4);
        }
#pragma unroll
        for (int k = 0; k < 8; k++) {
            U2 a01, a23, a45, a67;
            a01.v = *reinterpret_cast<const ulonglong2*>(&As[cur][k][8 * ty]);
            a23.v = *reinterpret_cast<const ulonglong2*>(&As[cur][k][8 * ty + 4]);
            a45.v = *reinterpret_cast<const ulonglong2*>(&As[cur][k][128 + 8 * ty]);
            a67.v = *reinterpret_cast<const ulonglong2*>(&As[cur][k][128 + 8 * ty + 4]);
            U2 b01, b23;
            b01.v = *reinterpret_cast<const ulonglong2*>(&Bs[cur][k][4 * tx]);
            b23.v = *reinterpret_cast<const ulonglong2*>(&Bs[cur][k][64 + 4 * tx]);
            ull am[8] = {a01.p[0], a01.p[1], a23.p[0], a23.p[1],
                         a45.p[0], a45.p[1], a67.p[0], a67.p[1]};
            ull bn[4] = {b01.p[0], b01.p[1], b23.p[0], b23.p[1]};
#pragma unroll
            for (int m = 0; m < 8; m++)
#pragma unroll
                for (int p = 0; p < 4; p++)
                    c[m][p] = fma2(am[m], bn[p], c[m][p]);
        }
        if (hasNext) {
            int nxt = 1 - cur;
            float4 d0 = make_float4(a4.a[0], a4.a[0], a4.a[1], a4.a[1]);
            float4 d1 = make_float4(a4.a[2], a4.a[2], a4.a[3], a4.a[3]);
            *reinterpret_cast<float4*>(&As[nxt][lk][2 * l4])     = d0;
            *reinterpret_cast<float4*>(&As[nxt][lk][2 * l4 + 4]) = d1;
            *reinterpret_cast<float4*>(&Bs[nxt][lk][l4]) = b4.v;
        }
        __syncthreads();
    }

    // epilogue: add v_template, store g_h[m][b]
#pragma unroll
    for (int m = 0; m < 8; m++) {
        int m_local = (m < 4) ? (4 * ty + m) : (64 + 4 * ty + (m - 4));
        int mg = mblk + m_local;
        if (mg >= MROWS) continue;
        float vt = v_template[mg];
        F4 o0, o1;
        unpack2(c[m][0], o0.a[0], o0.a[1]);
        unpack2(c[m][1], o0.a[2], o0.a[3]);
        unpack2(c[m][2], o1.a[0], o1.a[1]);
        unpack2(c[m][3], o1.a[2], o1.a[3]);
#pragma unroll
        for (int i = 0; i < 4; i++) { o0.a[i] += vt; o1.a[i] += vt; }
        *reinterpret_cast<float4*>(g_h + (size_t)mg * BS + bblk + 4 * tx)      = o0.v;
        *reinterpret_cast<float4*>(g_h + (size_t)mg * BS + bblk + 64 + 4 * tx) = o1.v;
    }
}

// ---------------- kernel 3: LBS blend, 2 v/warp, 4 b/lane ----------------
__global__ void __launch_bounds__(256, 3) k_lbs(const float* __restrict__ weights,
                                                float* __restrict__ out) {
    __shared__ float s_out[16 * RS];

    int warp = threadIdx.x >> 5;
    int lane = threadIdx.x & 31;
    int v0 = blockIdx.x * 16 + warp * 2;
    int v1 = v0 + 1;
    bool valid0 = (v0 < NV);
    bool valid1 = (v1 < NV);
    int v0c = valid0 ? v0 : (NV - 1);
    int v1c = valid1 ? v1 : (NV - 1);
    int b0 = blockIdx.y * 128 + lane * 4;

    // load h for both vertices
    F4 hA[3], hB[3];
#pragma unroll
    for (int d = 0; d < 3; d++) {
        hA[d].v = *reinterpret_cast<const float4*>(g_h + (size_t)(v0c * 3 + d) * BS + b0);
        hB[d].v = *reinterpret_cast<const float4*>(g_h + (size_t)(v1c * 3 + d) * BS + b0);
    }

    float rA0[4]={0,0,0,0}, rA1[4]={0,0,0,0}, rA2[4]={0,0,0,0};
    float rB0[4]={0,0,0,0}, rB1[4]={0,0,0,0}, rB2[4]={0,0,0,0};

#pragma unroll
    for (int j = 0; j < 16; j++) {
        float wA = weights[v0c * 16 + j];
        float wB = weights[v1c * 16 + j];
        const float* base = g_se3T + (j * 12) * BS + b0;
#pragma unroll
        for (int r = 0; r < 3; r++) {
            F4 m0, m1, m2, m3;
            m0.v = *reinterpret_cast<const float4*>(base + (r*4+0) * BS);
            m1.v = *reinterpret_cast<const float4*>(base + (r*4+1) * BS);
            m2.v = *reinterpret_cast<const float4*>(base + (r*4+2) * BS);
            m3.v = *reinterpret_cast<const float4*>(base + (r*4+3) * BS);
            float* rA = (r == 0) ? rA0 : (r == 1) ? rA1 : rA2;
            float* rB = (r == 0) ? rB0 : (r == 1) ? rB1 : rB2;
#pragma unroll
            for (int i = 0; i < 4; i++) {
                float tA = fmaf(m0.a[i], hA[0].a[i], fmaf(m1.a[i], hA[1].a[i],
                           fmaf(m2.a[i], hA[2].a[i], m3.a[i])));
                rA[i] = fmaf(wA, tA, rA[i]);
                float tB = fmaf(m0.a[i], hB[0].a[i], fmaf(m1.a[i], hB[1].a[i],
                           fmaf(m2.a[i], hB[2].a[i], m3.a[i])));
                rB[i] = fmaf(wB, tB, rB[i]);
            }
        }
    }

    F4 off0, off1, off2;
    off0.v = *reinterpret_cast<const float4*>(g_off + 0 * BS + b0);
    off1.v = *reinterpret_cast<const float4*>(g_off + 1 * BS + b0);
    off2.v = *reinterpret_cast<const float4*>(g_off + 2 * BS + b0);

    int posA = -1, posB = -1;
    if      (v0 == 745) posA = 4;
    else if (v0 == 333) posA = 8;
    else if (v0 == 444) posA = 12;
    else if (v0 == 555) posA = 16;
    else if (v0 == 672) posA = 20;
    if      (v1 == 745) posB = 4;
    else if (v1 == 333) posB = 8;
    else if (v1 == 444) posB = 12;
    else if (v1 == 555) posB = 16;
    else if (v1 == 672) posB = 20;

    int vl0 = warp * 2;
    int vl1 = vl0 + 1;
#pragma unroll
    for (int i = 0; i < 4; i++) {
        int bl = lane * 4 + i;
        float oA0 = rA0[i] + off0.a[i];
        float oA1 = rA1[i] + off1.a[i];
        float oA2 = rA2[i] + off2.a[i];
        float oB0 = rB0[i] + off0.a[i];
        float oB1 = rB1[i] + off1.a[i];
        float oB2 = rB2[i] + off2.a[i];
        if (valid0) {
            s_out[vl0 * RS + bl * 3 + 0] = oA0;
            s_out[vl0 * RS + bl * 3 + 1] = oA1;
            s_out[vl0 * RS + bl * 3 + 2] = oA2;
        }
        if (valid1) {
            s_out[vl1 * RS + bl * 3 + 0] = oB0;
            s_out[vl1 * RS + bl * 3 + 1] = oB1;
            s_out[vl1 * RS + bl * 3 + 2] = oB2;
        }
        if (posA >= 0) {
            int b = b0 + i;
            float* jo = out + (size_t)VOUT_ELEMS + ((size_t)b * 21 + posA) * 3;
            jo[0] = oA0; jo[1] = oA1; jo[2] = oA2;
        }
        if (posB >= 0) {
            int b = b0 + i;
            float* jo = out + (size_t)VOUT_ELEMS + ((size_t)b * 21 + posB) * 3;
            jo[0] = oB0; jo[1] = oB1; jo[2] = oB2;
        }
    }

    __syncthreads();

    int v_base = blockIdx.x * 16;
    int b_base = blockIdx.y * 128;
    int nv_here = NV - v_base;
    if (nv_here > 16) nv_here = 16;
    int row_floats = nv_here * 3;
#pragma unroll 4
    for (int t = threadIdx.x; t < 128 * 48; t += 256) {
        int b_local = t / 48;
        int e = t % 48;
        if (e < row_floats) {
            int v_local = e / 3;
            int d = e - v_local * 3;
            out[((size_t)(b_base + b_local) * NV + v_base) * 3 + e] =
                s_out[v_local * RS + b_local * 3 + d];
        }
    }
}

// ---------------- launch ----------------
extern "C" void kernel_launch(void* const* d_in, const int* in_sizes, int n_in,
                              void* d_out, int out_size) {
    const float* root_rotation = (const float*)d_in[0];
    const float* pose          = (const float*)d_in[1];
    const float* shape         = (const float*)d_in[2];
    const float* trans         = (const float*)d_in[3];
    const float* hc            = (const float*)d_in[4];
    const float* hm            = (const float*)d_in[5];
    const float* shapedirs     = (const float*)d_in[6];
    const float* posedirs      = (const float*)d_in[7];
    const float* v_template    = (const float*)d_in[8];
    const float* Jreg          = (const float*)d_in[9];
    const float* weights       = (const float*)d_in[10];
    float* out = (float*)d_out;

    k_build_dirsT<<<(KPAD * MP + 255) / 256, 256>>>(posedirs, shapedirs);
    k_jreg<<<48, 128>>>(Jreg, shapedirs, v_template);
    k_batch<<<BS / 128, 128>>>(root_rotation, pose, shape, trans, hc, hm,
                               out + VOUT_ELEMS);
    dim3 ggrid(BS / 128, 19);            // (n-blocks, m-blocks)
    k_gemm<<<ggrid, 256>>>(v_template);
    dim3 lgrid((NV + 15) / 16, BS / 128);
    k_lbs<<<lgrid, 256>>>(weights, out);
}

// round 9
// speedup vs baseline: 1.3293x; 1.2150x over previous
#include <cuda_runtime.h>
#include <math.h>

#define BS 4096
#define NV 778
#define KPAD 152                     // K padded to 19*8
#define MROWS 2334                   // NV*3
#define MP 2432                      // M padded to 19*128
#define VOUT_ELEMS (BS * NV * 3)
#define VT 64                        // vertices per lbs block
#define BT 32                        // batches per lbs block
#define NVP 832                      // NV padded to 13*64
#define SOS 97                       // s_out row stride

typedef unsigned long long ull;
union U2 { ulonglong2 v; ull p[2]; };
union F4 { float4 v; float a[4]; };
union P2 { float2 f; ull u; };

__device__ __forceinline__ ull fma2(ull a, ull b, ull c) {
    ull d;
    asm("fma.rn.f32x2 %0, %1, %2, %3;" : "=l"(d) : "l"(a), "l"(b), "l"(c));
    return d;
}
__device__ __forceinline__ ull add2(ull a, ull b) {
    ull d;
    asm("add.rn.f32x2 %0, %1, %2;" : "=l"(d) : "l"(a), "l"(b));
    return d;
}
__device__ __forceinline__ ull pack2(float x, float y) {
    ull d;
    asm("mov.b64 %0, {%1, %2};" : "=l"(d) : "f"(x), "f"(y));
    return d;
}
__device__ __forceinline__ void unpack2(ull p, float& x, float& y) {
    asm("mov.b64 {%0, %1}, %2;" : "=f"(x), "=f"(y) : "l"(p));
}

// ---------------- scratch ----------------
__device__ __align__(16) float g_dirsT[KPAD * MP];    // [k][m]
__device__ __align__(16) float g_featT[KPAD * BS];    // [k][b]
__device__ __align__(16) float g_h[MROWS * BS];       // [vd][b]
__device__ __align__(16) float g_se3T[192 * BS];      // [e][b]
__device__ __align__(16) float g_off[3 * BS];         // [d][b]
__device__ __align__(16) float g_wT[16 * NVP];        // [j][v] zero-padded
__device__ float g_JS[16 * 3 * 10];
__device__ float g_JT[16 * 3];

__constant__ int c_parent[16]   = {-1,0,1,2,0,4,5,0,7,8,0,10,11,0,13,14};
__constant__ int c_neworder[21] = {0,13,14,15,16,1,2,3,17,4,5,6,18,10,11,12,19,7,8,9,20};

// ---------------- kernel 0a: build transposed dirs ----------------
__global__ void k_build_dirsT(const float* __restrict__ posedirs,
                              const float* __restrict__ shapedirs) {
    int idx = blockIdx.x * blockDim.x + threadIdx.x;
    if (idx >= KPAD * MP) return;
    int m = idx % MP;
    int k = idx / MP;
    float val = 0.0f;
    if (m < MROWS) {
        if (k < 135)      val = posedirs[m * 135 + k];
        else if (k < 145) val = shapedirs[m * 10 + (k - 135)];
    }
    g_dirsT[idx] = val;
}

// ---------------- kernel 0c: transposed weights ----------------
__global__ void k_build_wT(const float* __restrict__ weights) {
    int idx = blockIdx.x * blockDim.x + threadIdx.x;
    if (idx >= 16 * NVP) return;
    int v = idx % NVP;
    int j = idx / NVP;
    g_wT[idx] = (v < NV) ? weights[v * 16 + j] : 0.0f;
}

// ---------------- kernel 0b: JS / JT ----------------
__global__ void k_jreg(const float* __restrict__ Jreg,
                       const float* __restrict__ shapedirs,
                       const float* __restrict__ v_template) {
    int jd = blockIdx.x;
    int j = jd / 3, d = jd % 3;
    int tid = threadIdx.x;
    float acc[11];
#pragma unroll
    for (int i = 0; i < 11; i++) acc[i] = 0.0f;
    for (int v = tid; v < NV; v += 128) {
        float r = Jreg[j * NV + v];
        const float* sd = shapedirs + (v * 3 + d) * 10;
#pragma unroll
        for (int s = 0; s < 10; s++) acc[s] = fmaf(r, sd[s], acc[s]);
        acc[10] = fmaf(r, v_template[v * 3 + d], acc[10]);
    }
    __shared__ float red[128][11];
#pragma unroll
    for (int i = 0; i < 11; i++) red[tid][i] = acc[i];
    __syncthreads();
    for (int off = 64; off > 0; off >>= 1) {
        if (tid < off) {
#pragma unroll
            for (int i = 0; i < 11; i++) red[tid][i] += red[tid + off][i];
        }
        __syncthreads();
    }
    if (tid == 0) {
#pragma unroll
        for (int s = 0; s < 10; s++) g_JS[jd * 10 + s] = red[0][s];
        g_JT[jd] = red[0][10];
    }
}

// ---------------- kernel 1: per-batch pose/rot/SE3 chain ----------------
__global__ void k_batch(const float* __restrict__ root_rotation,
                        const float* __restrict__ pose,
                        const float* __restrict__ shape,
                        const float* __restrict__ trans,
                        const float* __restrict__ hc,
                        const float* __restrict__ hm,
                        float* __restrict__ jout) {
    int b = blockIdx.x * blockDim.x + threadIdx.x;
    if (b >= BS) return;

    float pz[45];
#pragma unroll
    for (int c = 0; c < 45; c++) pz[c] = pose[b * 45 + c];

    float rot[15][9];
    for (int jj = 0; jj < 15; jj++) {
        float ax = hm[3 * jj], ay = hm[3 * jj + 1], az = hm[3 * jj + 2];
        for (int c = 0; c < 45; c++) {
            float p = pz[c];
            const float* h = hc + c * 45 + 3 * jj;
            ax = fmaf(p, h[0], ax);
            ay = fmaf(p, h[1], ay);
            az = fmaf(p, h[2], az);
        }
        float a2  = ax * ax + ay * ay + az * az + 1e-12f;
        float ang = sqrtf(a2);
        float inv = 1.0f / ang;
        float ux = ax * inv, uy = ay * inv, uz = az * inv;
        float cc = cosf(ang), ss = sinf(ang), oc = 1.0f - cc;
        float R00 = cc + oc * ux * ux;
        float R01 = -ss * uz + oc * ux * uy;
        float R02 =  ss * uy + oc * ux * uz;
        float R10 =  ss * uz + oc * ux * uy;
        float R11 = cc + oc * uy * uy;
        float R12 = -ss * ux + oc * uy * uz;
        float R20 = -ss * uy + oc * ux * uz;
        float R21 =  ss * ux + oc * uy * uz;
        float R22 = cc + oc * uz * uz;
        rot[jj][0]=R00; rot[jj][1]=R01; rot[jj][2]=R02;
        rot[jj][3]=R10; rot[jj][4]=R11; rot[jj][5]=R12;
        rot[jj][6]=R20; rot[jj][7]=R21; rot[jj][8]=R22;
        g_featT[(9*jj+0)*BS + b] = R00 - 1.0f;
        g_featT[(9*jj+1)*BS + b] = R01;
        g_featT[(9*jj+2)*BS + b] = R02;
        g_featT[(9*jj+3)*BS + b] = R10;
        g_featT[(9*jj+4)*BS + b] = R11 - 1.0f;
        g_featT[(9*jj+5)*BS + b] = R12;
        g_featT[(9*jj+6)*BS + b] = R20;
        g_featT[(9*jj+7)*BS + b] = R21;
        g_featT[(9*jj+8)*BS + b] = R22 - 1.0f;
    }

    float sh[10];
#pragma unroll
    for (int s = 0; s < 10; s++) {
        sh[s] = shape[b * 10 + s];
        g_featT[(135 + s) * BS + b] = sh[s];
    }
#pragma unroll
    for (int z = 145; z < KPAD; z++) g_featT[z * BS + b] = 0.0f;

    float jt[16][3];
    for (int j = 0; j < 16; j++) {
#pragma unroll
        for (int d = 0; d < 3; d++) {
            float a = g_JT[j * 3 + d];
            const float* js = g_JS + (j * 3 + d) * 10;
#pragma unroll
            for (int s = 0; s < 10; s++) a = fmaf(js[s], sh[s], a);
            jt[j][d] = a;
        }
    }

    float A[16][12];
    {
        float Rr[9];
#pragma unroll
        for (int i = 0; i < 9; i++) Rr[i] = root_rotation[b * 9 + i];
        float jx = jt[0][0], jy = jt[0][1], jz = jt[0][2];
#pragma unroll
        for (int r = 0; r < 3; r++) {
            A[0][r*4+0] = Rr[r*3+0];
            A[0][r*4+1] = Rr[r*3+1];
            A[0][r*4+2] = Rr[r*3+2];
        }
        A[0][3]  = jx - (Rr[0]*jx + Rr[1]*jy + Rr[2]*jz);
        A[0][7]  = jy - (Rr[3]*jx + Rr[4]*jy + Rr[5]*jz);
        A[0][11] = jz - (Rr[6]*jx + Rr[7]*jy + Rr[8]*jz);
    }
    for (int i = 1; i < 16; i++) {
        int p = c_parent[i];
        const float* Ri = rot[i - 1];
        float jx = jt[i][0], jy = jt[i][1], jz = jt[i][2];
        float t0 = jx - (Ri[0]*jx + Ri[1]*jy + Ri[2]*jz);
        float t1 = jy - (Ri[3]*jx + Ri[4]*jy + Ri[5]*jz);
        float t2 = jz - (Ri[6]*jx + Ri[7]*jy + Ri[8]*jz);
        const float* P = A[p];
        float* O = A[i];
#pragma unroll
        for (int r = 0; r < 3; r++) {
            float p0 = P[r*4+0], p1 = P[r*4+1], p2 = P[r*4+2];
            O[r*4+0] = p0*Ri[0] + p1*Ri[3] + p2*Ri[6];
            O[r*4+1] = p0*Ri[1] + p1*Ri[4] + p2*Ri[7];
            O[r*4+2] = p0*Ri[2] + p1*Ri[5] + p2*Ri[8];
            O[r*4+3] = p0*t0 + p1*t1 + p2*t2 + P[r*4+3];
        }
    }
    for (int j = 0; j < 16; j++)
#pragma unroll
        for (int e = 0; e < 12; e++) g_se3T[(j * 12 + e) * BS + b] = A[j][e];

    float cx = jt[0][0], cy = jt[0][1], cz = jt[0][2];
    float ox = trans[b*3+0] - cx, oy = trans[b*3+1] - cy, oz = trans[b*3+2] - cz;
    g_off[0*BS + b] = ox;
    g_off[1*BS + b] = oy;
    g_off[2*BS + b] = oz;

    float jl[16][3];
    jl[0][0] = cx; jl[0][1] = cy; jl[0][2] = cz;
    for (int i = 1; i < 16; i++) {
        int p = c_parent[i];
        const float* P = A[p];
        float jx = jt[i][0], jy = jt[i][1], jz = jt[i][2];
        jl[i][0] = P[0]*jx + P[1]*jy + P[2]*jz  + P[3];
        jl[i][1] = P[4]*jx + P[5]*jy + P[6]*jz  + P[7];
        jl[i][2] = P[8]*jx + P[9]*jy + P[10]*jz + P[11];
    }
    for (int pos = 0; pos < 21; pos++) {
        int src = c_neworder[pos];
        if (src < 16) {
            float* jo = jout + ((size_t)b * 21 + pos) * 3;
            jo[0] = jl[src][0] + ox;
            jo[1] = jl[src][1] + oy;
            jo[2] = jl[src][2] + oz;
        }
    }
}

// ---------------- kernel 2: tiled SGEMM (FFMA2): g_h = dirsT^T @ featT + vt ----------------
__global__ void __launch_bounds__(256, 2) k_gemm(const float* __restrict__ v_template) {
    __shared__ float As[2][8][256];
    __shared__ float Bs[2][8][128];

    int tid = threadIdx.x;
    int bblk = blockIdx.x * 128;
    int mblk = blockIdx.y * 128;
    int lk  = tid >> 5;
    int l4  = (tid & 31) * 4;

    int tx = tid & 15;
    int ty = tid >> 4;

    ull c[8][4];
#pragma unroll
    for (int m = 0; m < 8; m++)
#pragma unroll
        for (int p = 0; p < 4; p++) c[m][p] = 0ULL;

    F4 a4, b4;
    a4.v = *reinterpret_cast<const float4*>(g_dirsT + lk * MP + mblk + l4);
    b4.v = *reinterpret_cast<const float4*>(g_featT + lk * BS + bblk + l4);
    {
        float4 d0 = make_float4(a4.a[0], a4.a[0], a4.a[1], a4.a[1]);
        float4 d1 = make_float4(a4.a[2], a4.a[2], a4.a[3], a4.a[3]);
        *reinterpret_cast<float4*>(&As[0][lk][2 * l4])     = d0;
        *reinterpret_cast<float4*>(&As[0][lk][2 * l4 + 4]) = d1;
        *reinterpret_cast<float4*>(&Bs[0][lk][l4]) = b4.v;
    }
    __syncthreads();

    for (int s = 0; s < 19; s++) {
        int cur = s & 1;
        bool hasNext = (s + 1 < 19);
        if (hasNext) {
            a4.v = *reinterpret_cast<const float4*>(g_dirsT + ((s+1)*8 + lk) * MP + mblk + l4);
            b4.v = *reinterpret_cast<const float4*>(g_featT + ((s+1)*8 + lk) * BS + bblk + l4);
        }
#pragma unroll
        for (int k = 0; k < 8; k++) {
            U2 a01, a23, a45, a67;
            a01.v = *reinterpret_cast<const ulonglong2*>(&As[cur][k][8 * ty]);
            a23.v = *reinterpret_cast<const ulonglong2*>(&As[cur][k][8 * ty + 4]);
            a45.v = *reinterpret_cast<const ulonglong2*>(&As[cur][k][128 + 8 * ty]);
            a67.v = *reinterpret_cast<const ulonglong2*>(&As[cur][k][128 + 8 * ty + 4]);
            U2 b01, b23;
            b01.v = *reinterpret_cast<const ulonglong2*>(&Bs[cur][k][4 * tx]);
            b23.v = *reinterpret_cast<const ulonglong2*>(&Bs[cur][k][64 + 4 * tx]);
            ull am[8] = {a01.p[0], a01.p[1], a23.p[0], a23.p[1],
                         a45.p[0], a45.p[1], a67.p[0], a67.p[1]};
            ull bn[4] = {b01.p[0], b01.p[1], b23.p[0], b23.p[1]};
#pragma unroll
            for (int m = 0; m < 8; m++)
#pragma unroll
                for (int p = 0; p < 4; p++)
                    c[m][p] = fma2(am[m], bn[p], c[m][p]);
        }
        if (hasNext) {
            int nxt = 1 - cur;
            float4 d0 = make_float4(a4.a[0], a4.a[0], a4.a[1], a4.a[1]);
            float4 d1 = make_float4(a4.a[2], a4.a[2], a4.a[3], a4.a[3]);
            *reinterpret_cast<float4*>(&As[nxt][lk][2 * l4])     = d0;
            *reinterpret_cast<float4*>(&As[nxt][lk][2 * l4 + 4]) = d1;
            *reinterpret_cast<float4*>(&Bs[nxt][lk][l4]) = b4.v;
        }
        __syncthreads();
    }

#pragma unroll
    for (int m = 0; m < 8; m++) {
        int m_local = (m < 4) ? (4 * ty + m) : (64 + 4 * ty + (m - 4));
        int mg = mblk + m_local;
        if (mg >= MROWS) continue;
        float vt = v_template[mg];
        F4 o0, o1;
        unpack2(c[m][0], o0.a[0], o0.a[1]);
        unpack2(c[m][1], o0.a[2], o0.a[3]);
        unpack2(c[m][2], o1.a[0], o1.a[1]);
        unpack2(c[m][3], o1.a[2], o1.a[3]);
#pragma unroll
        for (int i = 0; i < 4; i++) { o0.a[i] += vt; o1.a[i] += vt; }
        *reinterpret_cast<float4*>(g_h + (size_t)mg * BS + bblk + 4 * tx)      = o0.v;
        *reinterpret_cast<float4*>(g_h + (size_t)mg * BS + bblk + 64 + 4 * tx) = o1.v;
    }
}

// ---------------- kernel 3: LBS blend — smem-staged SE3, 4 v x 1 b-pair / thread ----------------
__global__ void __launch_bounds__(256, 2) k_lbs(float* __restrict__ out) {
    __shared__ float sA[VT * SOS];     // 192x32 A tile (6144 floats); reused as s_out (64x97)
    __shared__ float sW[16 * VT];      // wT tile [j][v]

    int tid = threadIdx.x;
    int bx  = tid & 15;                // batch-pair index (0..15) -> 2 batches each
    int vg  = tid >> 4;                // vertex-group (0..15) -> 4 vertices each
    int vblk = blockIdx.x * VT;
    int bblk = blockIdx.y * BT;
    int b0 = bblk + bx * 2;
    int v0 = vblk + vg * 4;

    // cooperative load: A tile [192][BT] = 6144 floats = 1536 float4
#pragma unroll
    for (int t = tid; t < 192 * (BT / 4); t += 256) {
        int e = t >> 3;                // row 0..191
        int q = (t & 7) * 4;           // float offset 0,4,...,28
        *reinterpret_cast<float4*>(&sA[e * BT + q]) =
            *reinterpret_cast<const float4*>(g_se3T + (size_t)e * BS + bblk + q);
    }
    // cooperative load: wT tile [16][VT] = 1024 floats = 256 float4
    {
        int t = tid;
        int j = t >> 4, q = t & 15;
        *reinterpret_cast<float4*>(&sW[j * VT + q * 4]) =
            *reinterpret_cast<const float4*>(g_wT + j * NVP + vblk + q * 4);
    }

    // load h (v_tpose) for 4 vertices x 3 dims, packed pairs
    ull h[4][3];
#pragma unroll
    for (int u = 0; u < 4; u++) {
        int vv = v0 + u;
        if (vv > NV - 1) vv = NV - 1;
#pragma unroll
        for (int d = 0; d < 3; d++) {
            P2 t;
            t.f = *reinterpret_cast<const float2*>(g_h + (size_t)(vv * 3 + d) * BS + b0);
            h[u][d] = t.u;
        }
    }

    __syncthreads();

    ull acc[4][3];
#pragma unroll
    for (int u = 0; u < 4; u++)
#pragma unroll
        for (int r = 0; r < 3; r++) acc[u][r] = 0ULL;

#pragma unroll
    for (int j = 0; j < 16; j++) {
        F4 w4;
        w4.v = *reinterpret_cast<const float4*>(&sW[j * VT + vg * 4]);
        ull A[12];
#pragma unroll
        for (int e = 0; e < 12; e++)
            A[e] = *reinterpret_cast<const ull*>(&sA[(j * 12 + e) * BT + bx * 2]);
#pragma unroll
        for (int u = 0; u < 4; u++) {
            ull wp = pack2(w4.a[u], w4.a[u]);
#pragma unroll
            for (int r = 0; r < 3; r++) {
                ull t = fma2(A[r*4+0], h[u][0],
                        fma2(A[r*4+1], h[u][1],
                        fma2(A[r*4+2], h[u][2], A[r*4+3])));
                acc[u][r] = fma2(wp, t, acc[u][r]);
            }
        }
    }

    // offsets
    ull offp[3];
#pragma unroll
    for (int d = 0; d < 3; d++) {
        P2 t;
        t.f = *reinterpret_cast<const float2*>(g_off + d * BS + b0);
        offp[d] = t.u;
    }

    __syncthreads();   // all sA reads done; reuse as s_out
    float* s_out = sA;

#pragma unroll
    for (int u = 0; u < 4; u++) {
        int v = v0 + u;
        bool val = (v < NV);
        int pos = -1;
        if      (v == 745) pos = 4;
        else if (v == 333) pos = 8;
        else if (v == 444) pos = 12;
        else if (v == 555) pos = 16;
        else if (v == 672) pos = 20;
        float o[3][2];
#pragma unroll
        for (int r = 0; r < 3; r++) {
            ull s = add2(acc[u][r], offp[r]);
            unpack2(s, o[r][0], o[r][1]);
        }
        int vl = vg * 4 + u;
#pragma unroll
        for (int i = 0; i < 2; i++) {
            int bl = bx * 2 + i;
            if (val) {
                s_out[vl * SOS + bl * 3 + 0] = o[0][i];
                s_out[vl * SOS + bl * 3 + 1] = o[1][i];
                s_out[vl * SOS + bl * 3 + 2] = o[2][i];
            }
            if (pos >= 0) {
                int b = b0 + i;
                float* jo = out + (size_t)VOUT_ELEMS + ((size_t)b * 21 + pos) * 3;
                jo[0] = o[0][i]; jo[1] = o[1][i]; jo[2] = o[2][i];
            }
        }
    }

    __syncthreads();

    // coalesced readout: per batch, the block's vertices are contiguous in out
    int nv_here = NV - vblk;
    if (nv_here > VT) nv_here = VT;
    int row_floats = nv_here * 3;       // <= 192
#pragma unroll 4
    for (int t = tid; t < BT * (VT * 3); t += 256) {
        int bl = t / (VT * 3);
        int e  = t % (VT * 3);
        if (e < row_floats) {
            int vl = e / 3;
            int d  = e - vl * 3;
            out[((size_t)(bblk + bl) * NV + vblk) * 3 + e] =
                s_out[vl * SOS + bl * 3 + d];
        }
    }
}

// ---------------- launch ----------------
extern "C" void kernel_launch(void* const* d_in, const int* in_sizes, int n_in,
                              void* d_out, int out_size) {
    const float* root_rotation = (const float*)d_in[0];
    const float* pose          = (const float*)d_in[1];
    const float* shape         = (const float*)d_in[2];
    const float* trans         = (const float*)d_in[3];
    const float* hc            = (const float*)d_in[4];
    const float* hm            = (const float*)d_in[5];
    const float* shapedirs     = (const float*)d_in[6];
    const float* posedirs      = (const float*)d_in[7];
    const float* v_template    = (const float*)d_in[8];
    const float* Jreg          = (const float*)d_in[9];
    const float* weights       = (const float*)d_in[10];
    float* out = (float*)d_out;

    k_build_dirsT<<<(KPAD * MP + 255) / 256, 256>>>(posedirs, shapedirs);
    k_build_wT<<<(16 * NVP + 255) / 256, 256>>>(weights);
    k_jreg<<<48, 128>>>(Jreg, shapedirs, v_template);
    k_batch<<<BS / 128, 128>>>(root_rotation, pose, shape, trans, hc, hm,
                               out + VOUT_ELEMS);
    dim3 ggrid(BS / 128, 19);
    k_gemm<<<ggrid, 256>>>(v_template);
    dim3 lgrid((NV + VT - 1) / VT, BS / BT);
    k_lbs<<<lgrid, 256>>>(out);
}

// round 10
// speedup vs baseline: 1.4911x; 1.1217x over previous
#include <cuda_runtime.h>
#include <math.h>

#define BS 4096
#define NV 778
#define KPAD 152                     // K padded to 19*8
#define MROWS 2334                   // NV*3
#define MP 2432                      // M padded to 19*128
#define VOUT_ELEMS (BS * NV * 3)
#define VT 64                        // vertices per lbs block
#define BT 32                        // batches per lbs block
#define NVP 832                      // NV padded to 13*64
#define SOS 97                       // s_out row stride

typedef unsigned long long ull;
union U2 { ulonglong2 v; ull p[2]; };
union F4 { float4 v; float a[4]; };
union P2 { float2 f; ull u; };

__device__ __forceinline__ ull fma2(ull a, ull b, ull c) {
    ull d;
    asm("fma.rn.f32x2 %0, %1, %2, %3;" : "=l"(d) : "l"(a), "l"(b), "l"(c));
    return d;
}
__device__ __forceinline__ ull add2(ull a, ull b) {
    ull d;
    asm("add.rn.f32x2 %0, %1, %2;" : "=l"(d) : "l"(a), "l"(b));
    return d;
}
__device__ __forceinline__ ull pack2(float x, float y) {
    ull d;
    asm("mov.b64 %0, {%1, %2};" : "=l"(d) : "f"(x), "f"(y));
    return d;
}
__device__ __forceinline__ void unpack2(ull p, float& x, float& y) {
    asm("mov.b64 {%0, %1}, %2;" : "=f"(x), "=f"(y) : "l"(p));
}

// ---------------- scratch ----------------
__device__ __align__(16) float g_dirsT[KPAD * MP];    // [k][m]
__device__ __align__(16) float g_featT[KPAD * BS];    // [k][b]
__device__ __align__(16) float g_poseT[45 * BS];      // [c][b]
__device__ __align__(16) float g_h[MROWS * BS];       // [vd][b]
__device__ __align__(16) float g_se3T[192 * BS];      // [e][b]
__device__ __align__(16) float g_off[3 * BS];         // [d][b]
__device__ __align__(16) float g_wT[16 * NVP];        // [j][v]
__device__ float g_JS[16 * 3 * 10];
__device__ float g_JT[16 * 3];

__constant__ int c_parent[16]   = {-1,0,1,2,0,4,5,0,7,8,0,10,11,0,13,14};
__constant__ int c_src2pos[16]  = {0,5,6,7,9,10,11,17,18,19,13,14,15,1,2,3};

// ---------------- kernel 0a: build transposed dirs ----------------
__global__ void k_build_dirsT(const float* __restrict__ posedirs,
                              const float* __restrict__ shapedirs) {
    int idx = blockIdx.x * blockDim.x + threadIdx.x;
    if (idx >= KPAD * MP) return;
    int m = idx % MP;
    int k = idx / MP;
    float val = 0.0f;
    if (m < MROWS) {
        if (k < 135)      val = posedirs[m * 135 + k];
        else if (k < 145) val = shapedirs[m * 10 + (k - 135)];
    }
    g_dirsT[idx] = val;
}

// ---------------- kernel 0c: transposed weights ----------------
__global__ void k_build_wT(const float* __restrict__ weights) {
    int idx = blockIdx.x * blockDim.x + threadIdx.x;
    if (idx >= 16 * NVP) return;
    int v = idx % NVP;
    int j = idx / NVP;
    g_wT[idx] = (v < NV) ? weights[v * 16 + j] : 0.0f;
}

// ---------------- kernel 0d: transposed pose ----------------
__global__ void k_poseT(const float* __restrict__ pose) {
    int idx = blockIdx.x * blockDim.x + threadIdx.x;
    if (idx >= 45 * BS) return;
    int b = idx % BS;
    int c = idx / BS;
    g_poseT[idx] = pose[b * 45 + c];
}

// ---------------- kernel 0b: JS / JT ----------------
__global__ void k_jreg(const float* __restrict__ Jreg,
                       const float* __restrict__ shapedirs,
                       const float* __restrict__ v_template) {
    int jd = blockIdx.x;
    int j = jd / 3, d = jd % 3;
    int tid = threadIdx.x;
    float acc[11];
#pragma unroll
    for (int i = 0; i < 11; i++) acc[i] = 0.0f;
    for (int v = tid; v < NV; v += 128) {
        float r = Jreg[j * NV + v];
        const float* sd = shapedirs + (v * 3 + d) * 10;
#pragma unroll
        for (int s = 0; s < 10; s++) acc[s] = fmaf(r, sd[s], acc[s]);
        acc[10] = fmaf(r, v_template[v * 3 + d], acc[10]);
    }
    __shared__ float red[128][11];
#pragma unroll
    for (int i = 0; i < 11; i++) red[tid][i] = acc[i];
    __syncthreads();
    for (int off = 64; off > 0; off >>= 1) {
        if (tid < off) {
#pragma unroll
            for (int i = 0; i < 11; i++) red[tid][i] += red[tid + off][i];
        }
        __syncthreads();
    }
    if (tid == 0) {
#pragma unroll
        for (int s = 0; s < 10; s++) g_JS[jd * 10 + s] = red[0][s];
        g_JT[jd] = red[0][10];
    }
}

// ---------------- kernel 1a: per-(batch,joint) Rodrigues ----------------
__global__ void __launch_bounds__(256) k_rot(const float* __restrict__ hc,
                                             const float* __restrict__ hm) {
    int b  = blockIdx.x * 256 + threadIdx.x;
    int jj = blockIdx.y;   // 0..14

    float ax = hm[3 * jj], ay = hm[3 * jj + 1], az = hm[3 * jj + 2];
    for (int c = 0; c < 45; c++) {
        float p = g_poseT[c * BS + b];
        const float* h = hc + c * 45 + 3 * jj;
        ax = fmaf(p, h[0], ax);
        ay = fmaf(p, h[1], ay);
        az = fmaf(p, h[2], az);
    }
    float a2  = ax * ax + ay * ay + az * az + 1e-12f;
    float ang = sqrtf(a2);
    float inv = 1.0f / ang;
    float ux = ax * inv, uy = ay * inv, uz = az * inv;
    float cc = cosf(ang), ss = sinf(ang), oc = 1.0f - cc;
    float R00 = cc + oc * ux * ux;
    float R01 = -ss * uz + oc * ux * uy;
    float R02 =  ss * uy + oc * ux * uz;
    float R10 =  ss * uz + oc * ux * uy;
    float R11 = cc + oc * uy * uy;
    float R12 = -ss * ux + oc * uy * uz;
    float R20 = -ss * uy + oc * ux * uz;
    float R21 =  ss * ux + oc * uy * uz;
    float R22 = cc + oc * uz * uz;

    g_featT[(9*jj+0)*BS + b] = R00 - 1.0f;
    g_featT[(9*jj+1)*BS + b] = R01;
    g_featT[(9*jj+2)*BS + b] = R02;
    g_featT[(9*jj+3)*BS + b] = R10;
    g_featT[(9*jj+4)*BS + b] = R11 - 1.0f;
    g_featT[(9*jj+5)*BS + b] = R12;
    g_featT[(9*jj+6)*BS + b] = R20;
    g_featT[(9*jj+7)*BS + b] = R21;
    g_featT[(9*jj+8)*BS + b] = R22 - 1.0f;
}

// ---------------- kernel 1b: per-(batch,row) SE3 chain ----------------
__global__ void __launch_bounds__(128) k_chain(const float* __restrict__ root_rotation,
                                               const float* __restrict__ shape,
                                               const float* __restrict__ trans,
                                               float* __restrict__ jout) {
    int b = blockIdx.x * 128 + threadIdx.x;
    int r = blockIdx.y;   // 0..2

    float sh[10];
#pragma unroll
    for (int s = 0; s < 10; s++) sh[s] = shape[b * 10 + s];
    if (r == 0) {
#pragma unroll
        for (int s = 0; s < 10; s++) g_featT[(135 + s) * BS + b] = sh[s];
#pragma unroll
        for (int z = 145; z < KPAD; z++) g_featT[z * BS + b] = 0.0f;
    }

    // jt[0]
    float jt0[3];
#pragma unroll
    for (int d = 0; d < 3; d++) {
        float a = g_JT[d];
        const float* js = g_JS + d * 10;
#pragma unroll
        for (int s = 0; s < 10; s++) a = fmaf(js[s], sh[s], a);
        jt0[d] = a;
    }

    float A[16][4];
    // root: row r only needs row r of root_rotation
    {
        float R0 = root_rotation[b * 9 + r * 3 + 0];
        float R1 = root_rotation[b * 9 + r * 3 + 1];
        float R2 = root_rotation[b * 9 + r * 3 + 2];
        A[0][0] = R0; A[0][1] = R1; A[0][2] = R2;
        A[0][3] = jt0[r] - (R0 * jt0[0] + R1 * jt0[1] + R2 * jt0[2]);
    }

    float center = jt0[r];
    float off = trans[b * 3 + r] - center;
    g_off[r * BS + b] = off;

    // se3T for joint 0
#pragma unroll
    for (int c = 0; c < 4; c++) g_se3T[(0 * 12 + r * 4 + c) * BS + b] = A[0][c];
    // jout pos for src=0
    jout[((size_t)b * 21 + 0) * 3 + r] = center + off;

#pragma unroll
    for (int i = 1; i < 16; i++) {
        int p = c_parent[i];
        // jt[i] (lazy)
        float jx, jy, jz;
        {
            float a0 = g_JT[i * 3 + 0], a1 = g_JT[i * 3 + 1], a2 = g_JT[i * 3 + 2];
            const float* js0 = g_JS + (i * 3 + 0) * 10;
            const float* js1 = g_JS + (i * 3 + 1) * 10;
            const float* js2 = g_JS + (i * 3 + 2) * 10;
#pragma unroll
            for (int s = 0; s < 10; s++) {
                a0 = fmaf(js0[s], sh[s], a0);
                a1 = fmaf(js1[s], sh[s], a1);
                a2 = fmaf(js2[s], sh[s], a2);
            }
            jx = a0; jy = a1; jz = a2;
        }
        // R (from featT, add back identity)
        float R[9];
#pragma unroll
        for (int e = 0; e < 9; e++) R[e] = g_featT[(9 * (i - 1) + e) * BS + b];
        R[0] += 1.0f; R[4] += 1.0f; R[8] += 1.0f;

        float t0 = jx - (R[0]*jx + R[1]*jy + R[2]*jz);
        float t1 = jy - (R[3]*jx + R[4]*jy + R[5]*jz);
        float t2 = jz - (R[6]*jx + R[7]*jy + R[8]*jz);

        float p0 = A[p][0], p1 = A[p][1], p2 = A[p][2], p3 = A[p][3];
        A[i][0] = p0*R[0] + p1*R[3] + p2*R[6];
        A[i][1] = p0*R[1] + p1*R[4] + p2*R[7];
        A[i][2] = p0*R[2] + p1*R[5] + p2*R[8];
        A[i][3] = p0*t0 + p1*t1 + p2*t2 + p3;

#pragma unroll
        for (int c = 0; c < 4; c++) g_se3T[(i * 12 + r * 4 + c) * BS + b] = A[i][c];

        // joint output: jl[i] = SE3[p] row r applied to jt[i]
        float jl = p0*jx + p1*jy + p2*jz + p3;
        jout[((size_t)b * 21 + c_src2pos[i]) * 3 + r] = jl + off;
    }
}

// ---------------- kernel 2: tiled SGEMM (FFMA2): g_h = dirsT^T @ featT + vt ----------------
__global__ void __launch_bounds__(256, 2) k_gemm(const float* __restrict__ v_template) {
    __shared__ float As[2][8][256];
    __shared__ float Bs[2][8][128];

    int tid = threadIdx.x;
    int bblk = blockIdx.x * 128;
    int mblk = blockIdx.y * 128;
    int lk  = tid >> 5;
    int l4  = (tid & 31) * 4;

    int tx = tid & 15;
    int ty = tid >> 4;

    ull c[8][4];
#pragma unroll
    for (int m = 0; m < 8; m++)
#pragma unroll
        for (int p = 0; p < 4; p++) c[m][p] = 0ULL;

    F4 a4, b4;
    a4.v = *reinterpret_cast<const float4*>(g_dirsT + lk * MP + mblk + l4);
    b4.v = *reinterpret_cast<const float4*>(g_featT + lk * BS + bblk + l4);
    {
        float4 d0 = make_float4(a4.a[0], a4.a[0], a4.a[1], a4.a[1]);
        float4 d1 = make_float4(a4.a[2], a4.a[2], a4.a[3], a4.a[3]);
        *reinterpret_cast<float4*>(&As[0][lk][2 * l4])     = d0;
        *reinterpret_cast<float4*>(&As[0][lk][2 * l4 + 4]) = d1;
        *reinterpret_cast<float4*>(&Bs[0][lk][l4]) = b4.v;
    }
    __syncthreads();

    for (int s = 0; s < 19; s++) {
        int cur = s & 1;
        bool hasNext = (s + 1 < 19);
        if (hasNext) {
            a4.v = *reinterpret_cast<const float4*>(g_dirsT + ((s+1)*8 + lk) * MP + mblk + l4);
            b4.v = *reinterpret_cast<const float4*>(g_featT + ((s+1)*8 + lk) * BS + bblk + l4);
        }
#pragma unroll
        for (int k = 0; k < 8; k++) {
            U2 a01, a23, a45, a67;
            a01.v = *reinterpret_cast<const ulonglong2*>(&As[cur][k][8 * ty]);
            a23.v = *reinterpret_cast<const ulonglong2*>(&As[cur][k][8 * ty + 4]);
            a45.v = *reinterpret_cast<const ulonglong2*>(&As[cur][k][128 + 8 * ty]);
            a67.v = *reinterpret_cast<const ulonglong2*>(&As[cur][k][128 + 8 * ty + 4]);
            U2 b01, b23;
            b01.v = *reinterpret_cast<const ulonglong2*>(&Bs[cur][k][4 * tx]);
            b23.v = *reinterpret_cast<const ulonglong2*>(&Bs[cur][k][64 + 4 * tx]);
            ull am[8] = {a01.p[0], a01.p[1], a23.p[0], a23.p[1],
                         a45.p[0], a45.p[1], a67.p[0], a67.p[1]};
            ull bn[4] = {b01.p[0], b01.p[1], b23.p[0], b23.p[1]};
#pragma unroll
            for (int m = 0; m < 8; m++)
#pragma unroll
                for (int p = 0; p < 4; p++)
                    c[m][p] = fma2(am[m], bn[p], c[m][p]);
        }
        if (hasNext) {
            int nxt = 1 - cur;
            float4 d0 = make_float4(a4.a[0], a4.a[0], a4.a[1], a4.a[1]);
            float4 d1 = make_float4(a4.a[2], a4.a[2], a4.a[3], a4.a[3]);
            *reinterpret_cast<float4*>(&As[nxt][lk][2 * l4])     = d0;
            *reinterpret_cast<float4*>(&As[nxt][lk][2 * l4 + 4]) = d1;
            *reinterpret_cast<float4*>(&Bs[nxt][lk][l4]) = b4.v;
        }
        __syncthreads();
    }

#pragma unroll
    for (int m = 0; m < 8; m++) {
        int m_local = (m < 4) ? (4 * ty + m) : (64 + 4 * ty + (m - 4));
        int mg = mblk + m_local;
        if (mg >= MROWS) continue;
        float vt = v_template[mg];
        F4 o0, o1;
        unpack2(c[m][0], o0.a[0], o0.a[1]);
        unpack2(c[m][1], o0.a[2], o0.a[3]);
        unpack2(c[m][2], o1.a[0], o1.a[1]);
        unpack2(c[m][3], o1.a[2], o1.a[3]);
#pragma unroll
        for (int i = 0; i < 4; i++) { o0.a[i] += vt; o1.a[i] += vt; }
        *reinterpret_cast<float4*>(g_h + (size_t)mg * BS + bblk + 4 * tx)      = o0.v;
        *reinterpret_cast<float4*>(g_h + (size_t)mg * BS + bblk + 64 + 4 * tx) = o1.v;
    }
}

// ---------------- kernel 3: LBS blend — smem-staged SE3, 4 v x 1 b-pair / thread ----------------
__global__ void __launch_bounds__(256, 2) k_lbs(float* __restrict__ out) {
    __shared__ float sA[VT * SOS];
    __shared__ float sW[16 * VT];

    int tid = threadIdx.x;
    int bx  = tid & 15;
    int vg  = tid >> 4;
    int vblk = blockIdx.x * VT;
    int bblk = blockIdx.y * BT;
    int b0 = bblk + bx * 2;
    int v0 = vblk + vg * 4;

    // A tile [192][BT] = 1536 float4
#pragma unroll
    for (int t = tid; t < 192 * (BT / 4); t += 256) {
        int e = t >> 3;
        int q = (t & 7) * 4;
        *reinterpret_cast<float4*>(&sA[e * BT + q]) =
            *reinterpret_cast<const float4*>(g_se3T + (size_t)e * BS + bblk + q);
    }
    {
        int t = tid;
        int j = t >> 4, q = t & 15;
        *reinterpret_cast<float4*>(&sW[j * VT + q * 4]) =
            *reinterpret_cast<const float4*>(g_wT + j * NVP + vblk + q * 4);
    }

    ull h[4][3];
#pragma unroll
    for (int u = 0; u < 4; u++) {
        int vv = v0 + u;
        if (vv > NV - 1) vv = NV - 1;
#pragma unroll
        for (int d = 0; d < 3; d++) {
            P2 t;
            t.f = *reinterpret_cast<const float2*>(g_h + (size_t)(vv * 3 + d) * BS + b0);
            h[u][d] = t.u;
        }
    }

    __syncthreads();

    ull acc[4][3];
#pragma unroll
    for (int u = 0; u < 4; u++)
#pragma unroll
        for (int r = 0; r < 3; r++) acc[u][r] = 0ULL;

#pragma unroll
    for (int j = 0; j < 16; j++) {
        F4 w4;
        w4.v = *reinterpret_cast<const float4*>(&sW[j * VT + vg * 4]);
        ull A[12];
#pragma unroll
        for (int e = 0; e < 12; e++)
            A[e] = *reinterpret_cast<const ull*>(&sA[(j * 12 + e) * BT + bx * 2]);
#pragma unroll
        for (int u = 0; u < 4; u++) {
            ull wp = pack2(w4.a[u], w4.a[u]);
#pragma unroll
            for (int r = 0; r < 3; r++) {
                ull t = fma2(A[r*4+0], h[u][0],
                        fma2(A[r*4+1], h[u][1],
                        fma2(A[r*4+2], h[u][2], A[r*4+3])));
                acc[u][r] = fma2(wp, t, acc[u][r]);
            }
        }
    }

    ull offp[3];
#pragma unroll
    for (int d = 0; d < 3; d++) {
        P2 t;
        t.f = *reinterpret_cast<const float2*>(g_off + d * BS + b0);
        offp[d] = t.u;
    }

    __syncthreads();
    float* s_out = sA;

#pragma unroll
    for (int u = 0; u < 4; u++) {
        int v = v0 + u;
        bool val = (v < NV);
        int pos = -1;
        if      (v == 745) pos = 4;
        else if (v == 333) pos = 8;
        else if (v == 444) pos = 12;
        else if (v == 555) pos = 16;
        else if (v == 672) pos = 20;
        float o[3][2];
#pragma unroll
        for (int r = 0; r < 3; r++) {
            ull s = add2(acc[u][r], offp[r]);
            unpack2(s, o[r][0], o[r][1]);
        }
        int vl = vg * 4 + u;
#pragma unroll
        for (int i = 0; i < 2; i++) {
            int bl = bx * 2 + i;
            if (val) {
                s_out[vl * SOS + bl * 3 + 0] = o[0][i];
                s_out[vl * SOS + bl * 3 + 1] = o[1][i];
                s_out[vl * SOS + bl * 3 + 2] = o[2][i];
            }
            if (pos >= 0) {
                int b = b0 + i;
                float* jo = out + (size_t)VOUT_ELEMS + ((size_t)b * 21 + pos) * 3;
                jo[0] = o[0][i]; jo[1] = o[1][i]; jo[2] = o[2][i];
            }
        }
    }

    __syncthreads();

    int nv_here = NV - vblk;
    if (nv_here > VT) nv_here = VT;
    int row_floats = nv_here * 3;
#pragma unroll 4
    for (int t = tid; t < BT * (VT * 3); t += 256) {
        int bl = t / (VT * 3);
        int e  = t % (VT * 3);
        if (e < row_floats) {
            int vl = e / 3;
            int d  = e - vl * 3;
            out[((size_t)(bblk + bl) * NV + vblk) * 3 + e] =
                s_out[vl * SOS + bl * 3 + d];
        }
    }
}

// ---------------- launch ----------------
extern "C" void kernel_launch(void* const* d_in, const int* in_sizes, int n_in,
                              void* d_out, int out_size) {
    const float* root_rotation = (const float*)d_in[0];
    const float* pose          = (const float*)d_in[1];
    const float* shape         = (const float*)d_in[2];
    const float* trans         = (const float*)d_in[3];
    const float* hc            = (const float*)d_in[4];
    const float* hm            = (const float*)d_in[5];
    const float* shapedirs     = (const float*)d_in[6];
    const float* posedirs      = (const float*)d_in[7];
    const float* v_template    = (const float*)d_in[8];
    const float* Jreg          = (const float*)d_in[9];
    const float* weights       = (const float*)d_in[10];
    float* out = (float*)d_out;

    k_build_dirsT<<<(KPAD * MP + 255) / 256, 256>>>(posedirs, shapedirs);
    k_build_wT<<<(16 * NVP + 255) / 256, 256>>>(weights);
    k_poseT<<<(45 * BS + 255) / 256, 256>>>(pose);
    k_jreg<<<48, 128>>>(Jreg, shapedirs, v_template);

    dim3 rgrid(BS / 256, 15);
    k_rot<<<rgrid, 256>>>(hc, hm);
    dim3 cgrid(BS / 128, 3);
    k_chain<<<cgrid, 128>>>(root_rotation, shape, trans, out + VOUT_ELEMS);

    dim3 ggrid(BS / 128, 19);
    k_gemm<<<ggrid, 256>>>(v_template);
    dim3 lgrid((NV + VT - 1) / VT, BS / BT);
    k_lbs<<<lgrid, 256>>>(out);
}